// round 1
// baseline (speedup 1.0000x reference)
#include <cuda_runtime.h>
#include <math.h>

#define BB     2
#define NTOK   4096
#define DIM    768
#define HEADS  12
#define HD     64
#define HID    1536
#define HINTR  1024

// ---------------- device scratch (no allocations allowed) ----------------
__device__ int   g_edge[BB*NTOK];
__device__ int   g_raw[BB];
__device__ int   g_cntE[BB];
__device__ int   g_cntZ[BB];
__device__ int   g_eidx[BB*NTOK];
__device__ int   g_zidx[BB*NTOK];
__device__ float g_q  [(size_t)BB*HEADS*NTOK*HD];
__device__ float g_k  [(size_t)BB*HEADS*NTOK*HD];
__device__ float g_v  [(size_t)BB*HEADS*NTOK*HD];
__device__ float g_o  [(size_t)BB*NTOK*DIM];    // attention out, compacted [b][m][h*64+d]
__device__ float g_hln[(size_t)BB*NTOK*DIM];    // LN(x) easy rows, compacted
__device__ float g_h1 [(size_t)BB*NTOK*HID];    // gelu(gelu(fc1)), compacted
__device__ float g_h2 [(size_t)BB*NTOK*DIM];    // fc2 out, compacted
__device__ float g_pool[BB*DIM];
__device__ float g_sig [BB*DIM];

// ---------------- tiny setup kernels ----------------
__global__ void k_reset() {
    int i = threadIdx.x;
    if (i < BB) g_raw[i] = 0;
}

// one warp per token: mean over 16x16 pixel block of the hint
__global__ void k_edge(const float* __restrict__ hint) {
    int warp = threadIdx.x >> 5, lane = threadIdx.x & 31;
    int token = blockIdx.x * 8 + warp;         // grid = BB*NTOK/8
    int b = token / NTOK, t = token % NTOK;
    int ty = t >> 6, tx = t & 63;
    const float* base = hint + (size_t)b*HINTR*HINTR + (size_t)(ty*16)*HINTR + tx*16;
    int r = lane >> 1, half = lane & 1;
    const float4* p = (const float4*)(base + (size_t)r*HINTR + half*8);
    float4 a = p[0], c = p[1];
    float s = a.x+a.y+a.z+a.w + c.x+c.y+c.z+c.w;
    #pragma unroll
    for (int off = 16; off; off >>= 1) s += __shfl_down_sync(0xffffffffu, s, off);
    if (lane == 0) {
        float mean = s * (1.0f/256.0f);
        int e = (mean > 0.02f && mean < 0.98f) ? 1 : 0;
        g_edge[token] = e;
        if (e) atomicAdd(&g_raw[b], 1);
    }
}

__global__ void k_fallback() {
    int b = blockIdx.x;
    if (g_raw[b] >= 64) return;
    for (int t = threadIdx.x; t < NTOK; t += blockDim.x) g_edge[b*NTOK + t] = 1;
}

// one warp per batch: ballot-scan compaction into edge/easy index lists
__global__ void k_compact() {
    int b = blockIdx.x, lane = threadIdx.x;
    int ce = 0, cz = 0;
    for (int base = 0; base < NTOK; base += 32) {
        int t = base + lane;
        int f = g_edge[b*NTOK + t];
        unsigned bal = __ballot_sync(0xffffffffu, f);
        unsigned lt = (lane == 0) ? 0u : (0xffffffffu >> (32 - lane));
        if (f) g_eidx[b*NTOK + ce + __popc(bal  & lt)] = t;
        else   g_zidx[b*NTOK + cz + __popc(~bal & lt)] = t;
        int pe = __popc(bal);
        ce += pe; cz += 32 - pe;
    }
    if (lane == 0) { g_cntE[b] = ce; g_cntZ[b] = cz; }
}

// ---------------- generic tiled SGEMM: C[m][n] = sum_k A[m][k] * W[k][n] ----------------
// BM=BN=128, BK=16, 256 threads, 8x8 micro-tile per thread.
// EPI: 0 = QKV (gathered edge rows of x -> g_q/g_k/g_v)
//      1 = PROJ (g_o rows -> + bias + x residual, scatter to d_out at edge tokens)
//      2 = FC1  (g_hln rows -> bias + gelu(gelu()) -> g_h1)
//      3 = FC2  (g_h1 rows -> bias -> g_h2)
__device__ __forceinline__ float gelu_exact(float x) {
    return 0.5f * x * (1.0f + erff(x * 0.70710678118654752f));
}

template<int EPI>
__global__ void k_gemm(const float* __restrict__ xfull, const float* __restrict__ W,
                       const float* __restrict__ bias, float* __restrict__ dout)
{
    const int K = (EPI == 3) ? HID : DIM;
    const int N = (EPI == 0) ? 3*DIM : (EPI == 2 ? HID : DIM);
    const int* cntp = (EPI >= 2) ? g_cntZ : g_cntE;

    int b = blockIdx.z;
    int M = cntp[b];
    int m0 = blockIdx.y * 128;
    if (m0 >= M) return;
    int n0 = blockIdx.x * 128;

    const float* A;
    long astr;
    if (EPI == 0)      { A = xfull; astr = (long)NTOK*DIM; }
    else if (EPI == 1) { A = g_o;   astr = (long)NTOK*DIM; }
    else if (EPI == 2) { A = g_hln; astr = (long)NTOK*DIM; }
    else               { A = g_h1;  astr = (long)NTOK*HID; }
    A += (long)b * astr;

    __shared__ float As[16][128];
    __shared__ float Bs[16][128];

    int tid = threadIdx.x;
    int tx = tid & 15, ty = tid >> 4;

    // A load mapping: 512 float4 total; thread handles ids {tid, tid+256}
    const int rl0 = tid >> 2;           // 0..63
    const int rl1 = rl0 + 64;
    const int seg = (tid & 3) * 4;      // k sub-offset
    long aoff0 = -1, aoff1 = -1;
    {
        int gm0 = m0 + rl0, gm1 = m0 + rl1;
        if (gm0 < M) aoff0 = (long)((EPI == 0) ? g_eidx[b*NTOK + gm0] : gm0) * K;
        if (gm1 < M) aoff1 = (long)((EPI == 0) ? g_eidx[b*NTOK + gm1] : gm1) * K;
    }
    const int bkr0 = tid >> 5;          // 0..7
    const int bkr1 = bkr0 + 8;
    const int bcol = (tid & 31) * 4;

    float acc[8][8];
    #pragma unroll
    for (int i = 0; i < 8; i++)
        #pragma unroll
        for (int j = 0; j < 8; j++) acc[i][j] = 0.0f;

    for (int k0 = 0; k0 < K; k0 += 16) {
        float4 a0 = make_float4(0,0,0,0), a1 = a0;
        if (aoff0 >= 0) a0 = *(const float4*)(A + aoff0 + k0 + seg);
        if (aoff1 >= 0) a1 = *(const float4*)(A + aoff1 + k0 + seg);
        float4 b0 = *(const float4*)(W + (long)(k0 + bkr0)*N + n0 + bcol);
        float4 b1 = *(const float4*)(W + (long)(k0 + bkr1)*N + n0 + bcol);
        __syncthreads();
        As[seg+0][rl0] = a0.x; As[seg+1][rl0] = a0.y; As[seg+2][rl0] = a0.z; As[seg+3][rl0] = a0.w;
        As[seg+0][rl1] = a1.x; As[seg+1][rl1] = a1.y; As[seg+2][rl1] = a1.z; As[seg+3][rl1] = a1.w;
        *(float4*)&Bs[bkr0][bcol] = b0;
        *(float4*)&Bs[bkr1][bcol] = b1;
        __syncthreads();
        #pragma unroll
        for (int kk = 0; kk < 16; kk++) {
            float4 av0 = *(const float4*)&As[kk][ty*8];
            float4 av1 = *(const float4*)&As[kk][ty*8 + 4];
            float4 bv0 = *(const float4*)&Bs[kk][tx*8];
            float4 bv1 = *(const float4*)&Bs[kk][tx*8 + 4];
            float av[8] = {av0.x,av0.y,av0.z,av0.w, av1.x,av1.y,av1.z,av1.w};
            float bv[8] = {bv0.x,bv0.y,bv0.z,bv0.w, bv1.x,bv1.y,bv1.z,bv1.w};
            #pragma unroll
            for (int i = 0; i < 8; i++)
                #pragma unroll
                for (int j = 0; j < 8; j++) acc[i][j] += av[i] * bv[j];
        }
    }

    #pragma unroll
    for (int i = 0; i < 8; i++) {
        int m = m0 + ty*8 + i;
        if (m >= M) continue;
        #pragma unroll
        for (int j = 0; j < 8; j++) {
            int n = n0 + tx*8 + j;
            float val = acc[i][j] + bias[n];
            if (EPI == 0) {
                int part = n / DIM, cc = n % DIM;
                float* dst = (part == 0) ? g_q : (part == 1) ? g_k : g_v;
                int h = cc >> 6, d = cc & 63;
                dst[(((long)b*HEADS + h)*NTOK + m)*HD + d] = val;
            } else if (EPI == 1) {
                int tok = g_eidx[b*NTOK + m];
                long o = ((long)b*NTOK + tok)*DIM + n;
                dout[o] = val + xfull[o];
            } else if (EPI == 2) {
                g_h1[((long)b*NTOK + m)*HID + n] = gelu_exact(gelu_exact(val));
            } else {
                g_h2[((long)b*NTOK + m)*DIM + n] = val;
            }
        }
    }
}

// ---------------- flash attention over compacted edge tokens ----------------
// grid (NTOK/64, HEADS, BB), 64 threads; each thread owns one query row.
__global__ void k_attn() {
    int b = blockIdx.z, h = blockIdx.y;
    int M = g_cntE[b];
    int m0 = blockIdx.x * 64;
    if (m0 >= M) return;
    int t = threadIdx.x;
    long base = (((long)b*HEADS + h)*NTOK) * HD;
    bool act = (m0 + t) < M;

    float qr[HD];
    #pragma unroll
    for (int d = 0; d < HD; d++) qr[d] = 0.0f;
    if (act) {
        const float* qp = g_q + base + (long)(m0 + t)*HD;
        #pragma unroll
        for (int d = 0; d < HD; d++) qr[d] = qp[d] * 0.125f;  // 1/sqrt(64)
    }
    float acc[HD];
    #pragma unroll
    for (int d = 0; d < HD; d++) acc[d] = 0.0f;
    float mx = -3.0e38f, l = 0.0f;

    __shared__ float Ks[64][HD];
    __shared__ float Vs[64][HD];

    int ntiles = (M + 63) >> 6;
    for (int kt = 0; kt < ntiles; kt++) {
        int kbase = kt * 64;
        int kend = min(64, M - kbase);
        __syncthreads();
        for (int r = 0; r < kend; r++) {
            Ks[r][t] = g_k[base + (long)(kbase + r)*HD + t];
            Vs[r][t] = g_v[base + (long)(kbase + r)*HD + t];
        }
        __syncthreads();
        if (act) {
            for (int j = 0; j < kend; j++) {
                float s = 0.0f;
                #pragma unroll
                for (int d = 0; d < HD; d++) s += qr[d] * Ks[j][d];
                if (s > mx) {
                    float corr = __expf(mx - s);
                    mx = s; l *= corr;
                    #pragma unroll
                    for (int d = 0; d < HD; d++) acc[d] *= corr;
                }
                float p = __expf(s - mx);
                l += p;
                #pragma unroll
                for (int d = 0; d < HD; d++) acc[d] += p * Vs[j][d];
            }
        }
    }
    __syncthreads();
    float inv = act ? (1.0f / l) : 0.0f;
    #pragma unroll
    for (int d = 0; d < HD; d++) Ks[t][d] = acc[d] * inv;   // stage for coalesced store
    __syncthreads();
    int rows = min(64, M - m0);
    for (int r = 0; r < rows; r++)
        g_o[((long)b*NTOK + m0 + r)*DIM + h*HD + t] = Ks[r][t];
}

// ---------------- LayerNorm on easy rows ----------------
__global__ void k_ln(const float* __restrict__ x, const float* __restrict__ g,
                     const float* __restrict__ be) {
    int b = blockIdx.y, m = blockIdx.x;
    if (m >= g_cntZ[b]) return;
    int tok = g_zidx[b*NTOK + m];
    const float* row = x + ((long)b*NTOK + tok)*DIM;
    int tid = threadIdx.x;
    float v[3];
    float s = 0.0f, s2 = 0.0f;
    #pragma unroll
    for (int i = 0; i < 3; i++) {
        v[i] = row[tid + i*256];
        s += v[i]; s2 += v[i]*v[i];
    }
    __shared__ float r0[256], r1[256];
    r0[tid] = s; r1[tid] = s2;
    __syncthreads();
    for (int off = 128; off; off >>= 1) {
        if (tid < off) { r0[tid] += r0[tid+off]; r1[tid] += r1[tid+off]; }
        __syncthreads();
    }
    float mu  = r0[0] * (1.0f/DIM);
    float var = r1[0] * (1.0f/DIM) - mu*mu;
    float rs  = rsqrtf(var + 1e-5f);
    float* outp = g_hln + ((long)b*NTOK + m)*DIM;
    #pragma unroll
    for (int i = 0; i < 3; i++) {
        int c = tid + i*256;
        outp[c] = (v[i] - mu) * rs * g[c] + be[c];
    }
}

// ---------------- masked mean pool over easy rows ----------------
__global__ void k_pool() {
    int b = blockIdx.y;
    int c = blockIdx.x * 256 + threadIdx.x;
    int cz = g_cntZ[b];
    float s = 0.0f;
    for (int m = 0; m < cz; m++) s += g_h2[((long)b*NTOK + m)*DIM + c];
    g_pool[b*DIM + c] = s / fmaxf((float)cz, 1.0f);
}

// ---------------- ECA conv(k=5, SAME) + sigmoid ----------------
__global__ void k_eca(const float* __restrict__ w) {
    int b = blockIdx.x, c = threadIdx.x;   // block = 768 threads
    float g = 0.0f;
    #pragma unroll
    for (int tt = 0; tt < 5; tt++) {
        int cc = c + tt - 2;
        if (cc >= 0 && cc < DIM) g += w[tt] * g_pool[b*DIM + cc];
    }
    g_sig[b*DIM + c] = 1.0f / (1.0f + __expf(-g));
}

// ---------------- LTRM scatter: out = x + h2 * sig at easy tokens ----------------
__global__ void k_ltrm(const float* __restrict__ x, float* __restrict__ out) {
    int b = blockIdx.y, m = blockIdx.x;
    if (m >= g_cntZ[b]) return;
    int tok = g_zidx[b*NTOK + m];
    long ro = ((long)b*NTOK + tok)*DIM;
    long ri = ((long)b*NTOK + m)*DIM;
    for (int c = threadIdx.x; c < DIM; c += 256)
        out[ro + c] = x[ro + c] + g_h2[ri + c] * g_sig[b*DIM + c];
}

// ---------------- launch ----------------
extern "C" void kernel_launch(void* const* d_in, const int* in_sizes, int n_in,
                              void* d_out, int out_size) {
    const float* x      = (const float*)d_in[0];
    const float* hint   = (const float*)d_in[1];
    const float* qkv_w  = (const float*)d_in[2];
    const float* qkv_b  = (const float*)d_in[3];
    const float* proj_w = (const float*)d_in[4];
    const float* proj_b = (const float*)d_in[5];
    const float* ln_g   = (const float*)d_in[6];
    const float* ln_b   = (const float*)d_in[7];
    const float* fc1_w  = (const float*)d_in[8];
    const float* fc1_b  = (const float*)d_in[9];
    const float* fc2_w  = (const float*)d_in[10];
    const float* fc2_b  = (const float*)d_in[11];
    const float* eca_w  = (const float*)d_in[12];
    float* out = (float*)d_out;

    k_reset   <<<1, 32>>>();
    k_edge    <<<BB*NTOK/8, 256>>>(hint);
    k_fallback<<<BB, 256>>>();
    k_compact <<<BB, 32>>>();

    // edge path
    k_gemm<0><<<dim3(3*DIM/128, NTOK/128, BB), 256>>>(x, qkv_w, qkv_b, out);
    k_attn   <<<dim3(NTOK/64, HEADS, BB), 64>>>();
    k_gemm<1><<<dim3(DIM/128, NTOK/128, BB), 256>>>(x, proj_w, proj_b, out);

    // easy path (LTRM)
    k_ln     <<<dim3(NTOK, BB), 256>>>(x, ln_g, ln_b);
    k_gemm<2><<<dim3(HID/128, NTOK/128, BB), 256>>>(x, fc1_w, fc1_b, out);
    k_gemm<3><<<dim3(DIM/128, NTOK/128, BB), 256>>>(x, fc2_w, fc2_b, out);
    k_pool   <<<dim3(DIM/256, BB), 256>>>();
    k_eca    <<<BB, DIM>>>(eca_w);
    k_ltrm   <<<dim3(NTOK, BB), 256>>>(x, out);
}

// round 2
// speedup vs baseline: 2.5649x; 2.5649x over previous
#include <cuda_runtime.h>
#include <math.h>

#define BB     2
#define NTOK   4096
#define DIM    768
#define HEADS  12
#define HD     64
#define HID    1536
#define HINTR  1024

// ---------------- device scratch ----------------
__device__ int   g_edge[BB*NTOK];
__device__ int   g_raw[BB];
__device__ int   g_cntE[BB];
__device__ int   g_cntZ[BB];
__device__ int   g_eidx[BB*NTOK];
__device__ int   g_zidx[BB*NTOK];
__device__ float g_q  [(size_t)BB*HEADS*NTOK*HD];
__device__ float g_k  [(size_t)BB*HEADS*NTOK*HD];
__device__ float g_v  [(size_t)BB*HEADS*NTOK*HD];
__device__ float g_o  [(size_t)BB*NTOK*DIM];
__device__ float g_hln[(size_t)BB*NTOK*DIM];
__device__ float g_h1 [(size_t)BB*NTOK*HID];
__device__ float g_h2 [(size_t)BB*NTOK*DIM];
__device__ float g_pool[BB*DIM];
__device__ float g_sig [BB*DIM];

// ---------------- tf32 mma helpers ----------------
__device__ __forceinline__ unsigned f2tf(float x) {
    unsigned r;
    asm("cvt.rna.tf32.f32 %0, %1;" : "=r"(r) : "f"(x));
    return r;
}
__device__ __forceinline__ void mma8(float4& d, const unsigned* a, unsigned b0, unsigned b1) {
    asm volatile(
        "mma.sync.aligned.m16n8k8.row.col.f32.tf32.tf32.f32 "
        "{%0,%1,%2,%3}, {%4,%5,%6,%7}, {%8,%9}, {%0,%1,%2,%3};\n"
        : "+f"(d.x), "+f"(d.y), "+f"(d.z), "+f"(d.w)
        : "r"(a[0]), "r"(a[1]), "r"(a[2]), "r"(a[3]), "r"(b0), "r"(b1));
}

// ---------------- tiny setup kernels ----------------
__global__ void k_reset() {
    int i = threadIdx.x;
    if (i < BB) g_raw[i] = 0;
}

__global__ void k_edge(const float* __restrict__ hint) {
    int warp = threadIdx.x >> 5, lane = threadIdx.x & 31;
    int token = blockIdx.x * 8 + warp;
    int b = token / NTOK, t = token % NTOK;
    int ty = t >> 6, tx = t & 63;
    const float* base = hint + (size_t)b*HINTR*HINTR + (size_t)(ty*16)*HINTR + tx*16;
    int r = lane >> 1, half = lane & 1;
    const float4* p = (const float4*)(base + (size_t)r*HINTR + half*8);
    float4 a = p[0], c = p[1];
    float s = a.x+a.y+a.z+a.w + c.x+c.y+c.z+c.w;
    #pragma unroll
    for (int off = 16; off; off >>= 1) s += __shfl_down_sync(0xffffffffu, s, off);
    if (lane == 0) {
        float mean = s * (1.0f/256.0f);
        int e = (mean > 0.02f && mean < 0.98f) ? 1 : 0;
        g_edge[token] = e;
        if (e) atomicAdd(&g_raw[b], 1);
    }
}

__global__ void k_fallback() {
    int b = blockIdx.x;
    if (g_raw[b] >= 64) return;
    for (int t = threadIdx.x; t < NTOK; t += blockDim.x) g_edge[b*NTOK + t] = 1;
}

// parallel ordered compaction: 1 block of 1024 threads per batch
__global__ void k_compact() {
    int b = blockIdx.x, tid = threadIdx.x;
    int t0 = tid * 4;
    int f[4]; int e = 0;
    #pragma unroll
    for (int i = 0; i < 4; i++) { f[i] = g_edge[b*NTOK + t0 + i]; e += f[i]; }
    int lane = tid & 31, wid = tid >> 5;
    int v = e;
    #pragma unroll
    for (int off = 1; off < 32; off <<= 1) {
        int n = __shfl_up_sync(0xffffffffu, v, off);
        if (lane >= off) v += n;
    }
    __shared__ int wsum[32];
    if (lane == 31) wsum[wid] = v;
    __syncthreads();
    if (wid == 0) {
        int wv = wsum[lane];
        #pragma unroll
        for (int off = 1; off < 32; off <<= 1) {
            int n = __shfl_up_sync(0xffffffffu, wv, off);
            if (lane >= off) wv += n;
        }
        wsum[lane] = wv;
    }
    __syncthreads();
    int excl = v - e + (wid ? wsum[wid-1] : 0);
    int eoff = excl, zoff = t0 - excl;
    #pragma unroll
    for (int i = 0; i < 4; i++) {
        if (f[i]) g_eidx[b*NTOK + eoff++] = t0 + i;
        else      g_zidx[b*NTOK + zoff++] = t0 + i;
    }
    if (tid == 1023) { int tot = wsum[31]; g_cntE[b] = tot; g_cntZ[b] = NTOK - tot; }
}

// ---------------- tf32 MMA GEMM: C = A @ W (+bias, epilogue) ----------------
// BM=128 BN=128 BK=16, 256 thr = 8 warps (2m x 4n), warp tile 64x32.
__device__ __forceinline__ float gelu_exact(float x) {
    return 0.5f * x * (1.0f + erff(x * 0.70710678118654752f));
}

template<int EPI>
__global__ void k_gemm(const float* __restrict__ xfull, const float* __restrict__ W,
                       const float* __restrict__ bias, float* __restrict__ dout)
{
    constexpr int K = (EPI == 3) ? HID : DIM;
    constexpr int N = (EPI == 0) ? 3*DIM : (EPI == 2 ? HID : DIM);
    const int* cntp = (EPI >= 2) ? g_cntZ : g_cntE;

    int b = blockIdx.z;
    int M = cntp[b];
    int m0 = blockIdx.y * 128;
    if (m0 >= M) return;
    int n0 = blockIdx.x * 128;

    const float* A;
    if (EPI == 0)      A = xfull + (long)b*NTOK*DIM;
    else if (EPI == 1) A = g_o   + (long)b*NTOK*DIM;
    else if (EPI == 2) A = g_hln + (long)b*NTOK*DIM;
    else               A = g_h1  + (long)b*NTOK*HID;

    __shared__ unsigned As[128][20];   // [m][k], stride 20 -> conflict-free frags
    __shared__ unsigned Bs[16][136];   // [k][n], stride 136 -> conflict-free frags

    int tid = threadIdx.x;
    int w = tid >> 5, lane = tid & 31;
    int wm = (w >> 2) * 64, wn = (w & 3) * 32;
    int qr = lane >> 2, qc = lane & 3;

    // A-load tasks: task = tid + 256*t : m = task>>2, kc = task&3
    int  mloc[2], kcid[2];
    long arow[2];
    #pragma unroll
    for (int t = 0; t < 2; t++) {
        int task = tid + 256*t;
        mloc[t] = task >> 2; kcid[t] = task & 3;
        int gm = m0 + mloc[t];
        if (gm < M) arow[t] = (long)((EPI == 0) ? g_eidx[b*NTOK + gm] : gm) * K;
        else        arow[t] = -1;
    }
    // B-load tasks: kr = task>>5 (0..15), nc = (task&31)*4
    int krB[2], ncB[2];
    #pragma unroll
    for (int t = 0; t < 2; t++) {
        int task = tid + 256*t;
        krB[t] = task >> 5; ncB[t] = (task & 31) * 4;
    }

    float4 acc[4][4];
    #pragma unroll
    for (int i = 0; i < 4; i++)
        #pragma unroll
        for (int j = 0; j < 4; j++) acc[i][j] = make_float4(0,0,0,0);

    for (int k0 = 0; k0 < K; k0 += 16) {
        float4 av[2], bv[2];
        #pragma unroll
        for (int t = 0; t < 2; t++) {
            av[t] = make_float4(0,0,0,0);
            if (arow[t] >= 0) av[t] = *(const float4*)(A + arow[t] + k0 + kcid[t]*4);
            bv[t] = *(const float4*)(W + (long)(k0 + krB[t])*N + n0 + ncB[t]);
        }
        __syncthreads();
        #pragma unroll
        for (int t = 0; t < 2; t++) {
            *(uint4*)&As[mloc[t]][kcid[t]*4] =
                make_uint4(f2tf(av[t].x), f2tf(av[t].y), f2tf(av[t].z), f2tf(av[t].w));
            *(uint4*)&Bs[krB[t]][ncB[t]] =
                make_uint4(f2tf(bv[t].x), f2tf(bv[t].y), f2tf(bv[t].z), f2tf(bv[t].w));
        }
        __syncthreads();
        #pragma unroll
        for (int kk = 0; kk < 16; kk += 8) {
            unsigned af[4][4];
            #pragma unroll
            for (int mi = 0; mi < 4; mi++) {
                int mb = wm + mi*16;
                af[mi][0] = As[mb + qr    ][kk + qc];
                af[mi][1] = As[mb + qr + 8][kk + qc];
                af[mi][2] = As[mb + qr    ][kk + qc + 4];
                af[mi][3] = As[mb + qr + 8][kk + qc + 4];
            }
            #pragma unroll
            for (int ni = 0; ni < 4; ni++) {
                unsigned b0 = Bs[kk + qc    ][wn + ni*8 + qr];
                unsigned b1 = Bs[kk + qc + 4][wn + ni*8 + qr];
                #pragma unroll
                for (int mi = 0; mi < 4; mi++) mma8(acc[mi][ni], af[mi], b0, b1);
            }
        }
    }

    // epilogue
    #pragma unroll
    for (int mi = 0; mi < 4; mi++) {
        int rowA = m0 + wm + mi*16 + qr;
        int rowB = rowA + 8;
        #pragma unroll
        for (int ni = 0; ni < 4; ni++) {
            int col = n0 + wn + ni*8 + qc*2;
            float b0v = bias[col], b1v = bias[col+1];
            float vx = acc[mi][ni].x + b0v, vy = acc[mi][ni].y + b1v;
            float vz = acc[mi][ni].z + b0v, vw = acc[mi][ni].w + b1v;
            if (EPI == 0) {
                int part = col / DIM, cc = col - part*DIM;
                float* dst = (part == 0) ? g_q : (part == 1) ? g_k : g_v;
                int h = cc >> 6, d = cc & 63;
                long hb = ((long)b*HEADS + h)*NTOK;
                if (rowA < M) *(float2*)&dst[(hb + rowA)*HD + d] = make_float2(vx, vy);
                if (rowB < M) *(float2*)&dst[(hb + rowB)*HD + d] = make_float2(vz, vw);
            } else if (EPI == 1) {
                if (rowA < M) {
                    long o = ((long)b*NTOK + g_eidx[b*NTOK + rowA])*DIM + col;
                    *(float2*)&dout[o] = make_float2(vx + xfull[o], vy + xfull[o+1]);
                }
                if (rowB < M) {
                    long o = ((long)b*NTOK + g_eidx[b*NTOK + rowB])*DIM + col;
                    *(float2*)&dout[o] = make_float2(vz + xfull[o], vw + xfull[o+1]);
                }
            } else if (EPI == 2) {
                if (rowA < M) *(float2*)&g_h1[((long)b*NTOK + rowA)*HID + col] =
                    make_float2(gelu_exact(gelu_exact(vx)), gelu_exact(gelu_exact(vy)));
                if (rowB < M) *(float2*)&g_h1[((long)b*NTOK + rowB)*HID + col] =
                    make_float2(gelu_exact(gelu_exact(vz)), gelu_exact(gelu_exact(vw)));
            } else {
                if (rowA < M) *(float2*)&g_h2[((long)b*NTOK + rowA)*DIM + col] = make_float2(vx, vy);
                if (rowB < M) *(float2*)&g_h2[((long)b*NTOK + rowB)*DIM + col] = make_float2(vz, vw);
            }
        }
    }
}

// ---------------- tf32 flash attention ----------------
// 128 thr (4 warps), 64 queries/block (16/warp), 48-key tiles.
#define KT 48
__global__ void k_attn() {
    int b = blockIdx.z, h = blockIdx.y;
    int M = g_cntE[b];
    int m0 = blockIdx.x * 64;
    if (m0 >= M) return;
    int tid = threadIdx.x, w = tid >> 5, lane = tid & 31;
    int qr = lane >> 2, qc = lane & 3;
    long base = ((long)b*HEADS + h)*NTOK*HD;

    __shared__ unsigned Ks[KT][68];
    __shared__ unsigned Vs[KT][72];
    __shared__ unsigned Ps[64][52];

    // Q fragments in registers (16 rows per warp), pre-scaled
    int r0 = m0 + w*16 + qr, r1 = r0 + 8;
    bool v0 = r0 < M, v1 = r1 < M;
    const float* q0p = g_q + base + (long)r0*HD;
    const float* q1p = g_q + base + (long)r1*HD;
    unsigned qf[8][4];
    #pragma unroll
    for (int ks = 0; ks < 8; ks++) {
        int c = ks*8 + qc;
        qf[ks][0] = f2tf(v0 ? q0p[c]   * 0.125f : 0.0f);
        qf[ks][1] = f2tf(v1 ? q1p[c]   * 0.125f : 0.0f);
        qf[ks][2] = f2tf(v0 ? q0p[c+4] * 0.125f : 0.0f);
        qf[ks][3] = f2tf(v1 ? q1p[c+4] * 0.125f : 0.0f);
    }

    float4 oacc[8];
    #pragma unroll
    for (int i = 0; i < 8; i++) oacc[i] = make_float4(0,0,0,0);
    float mx0 = -1e30f, mx1 = -1e30f, l0 = 0.0f, l1 = 0.0f;

    int ntiles = (M + KT - 1) / KT;
    for (int kt = 0; kt < ntiles; kt++) {
        int kb = kt * KT;
        int kend = min(KT, M - kb);
        __syncthreads();
        // load K/V tile (zero-fill tail rows)
        for (int i = tid; i < KT*16; i += 128) {
            int krow = i >> 4, d4 = (i & 15) * 4;
            float4 kv = make_float4(0,0,0,0), vv = make_float4(0,0,0,0);
            if (krow < kend) {
                kv = *(const float4*)(g_k + base + (long)(kb + krow)*HD + d4);
                vv = *(const float4*)(g_v + base + (long)(kb + krow)*HD + d4);
            }
            *(uint4*)&Ks[krow][d4] = make_uint4(f2tf(kv.x), f2tf(kv.y), f2tf(kv.z), f2tf(kv.w));
            *(uint4*)&Vs[krow][d4] = make_uint4(f2tf(vv.x), f2tf(vv.y), f2tf(vv.z), f2tf(vv.w));
        }
        __syncthreads();

        // S = Q K^T : 6 n-tiles of 8 keys
        float4 s[6];
        #pragma unroll
        for (int nt = 0; nt < 6; nt++) s[nt] = make_float4(0,0,0,0);
        #pragma unroll
        for (int ks = 0; ks < 8; ks++) {
            #pragma unroll
            for (int nt = 0; nt < 6; nt++) {
                unsigned b0 = Ks[nt*8 + qr][ks*8 + qc];
                unsigned b1 = Ks[nt*8 + qr][ks*8 + qc + 4];
                mma8(s[nt], qf[ks], b0, b1);
            }
        }
        // mask + row max
        float t0 = -1e30f, t1 = -1e30f;
        #pragma unroll
        for (int nt = 0; nt < 6; nt++) {
            int c0 = kb + nt*8 + qc*2;
            if (c0     >= M) { s[nt].x = -1e30f; s[nt].z = -1e30f; }
            if (c0 + 1 >= M) { s[nt].y = -1e30f; s[nt].w = -1e30f; }
            t0 = fmaxf(t0, fmaxf(s[nt].x, s[nt].y));
            t1 = fmaxf(t1, fmaxf(s[nt].z, s[nt].w));
        }
        t0 = fmaxf(t0, __shfl_xor_sync(0xffffffffu, t0, 1));
        t0 = fmaxf(t0, __shfl_xor_sync(0xffffffffu, t0, 2));
        t1 = fmaxf(t1, __shfl_xor_sync(0xffffffffu, t1, 1));
        t1 = fmaxf(t1, __shfl_xor_sync(0xffffffffu, t1, 2));
        float nm0 = fmaxf(mx0, t0), nm1 = fmaxf(mx1, t1);
        float cr0 = __expf(mx0 - nm0), cr1 = __expf(mx1 - nm1);
        l0 *= cr0; l1 *= cr1;
        #pragma unroll
        for (int i = 0; i < 8; i++) {
            oacc[i].x *= cr0; oacc[i].y *= cr0;
            oacc[i].z *= cr1; oacc[i].w *= cr1;
        }
        mx0 = nm0; mx1 = nm1;

        float ps0 = 0.0f, ps1 = 0.0f;
        int prow0 = w*16 + qr, prow1 = prow0 + 8;
        #pragma unroll
        for (int nt = 0; nt < 6; nt++) {
            float px = __expf(s[nt].x - mx0), py = __expf(s[nt].y - mx0);
            float pz = __expf(s[nt].z - mx1), pw = __expf(s[nt].w - mx1);
            ps0 += px + py; ps1 += pz + pw;
            int cc = nt*8 + qc*2;
            *(uint2*)&Ps[prow0][cc] = make_uint2(f2tf(px), f2tf(py));
            *(uint2*)&Ps[prow1][cc] = make_uint2(f2tf(pz), f2tf(pw));
        }
        ps0 += __shfl_xor_sync(0xffffffffu, ps0, 1);
        ps0 += __shfl_xor_sync(0xffffffffu, ps0, 2);
        ps1 += __shfl_xor_sync(0xffffffffu, ps1, 1);
        ps1 += __shfl_xor_sync(0xffffffffu, ps1, 2);
        l0 += ps0; l1 += ps1;
        __syncwarp();

        // O += P V : 6 k-steps, 8 n-tiles over HD
        #pragma unroll
        for (int ks = 0; ks < 6; ks++) {
            unsigned pf[4];
            pf[0] = Ps[prow0][ks*8 + qc];
            pf[1] = Ps[prow1][ks*8 + qc];
            pf[2] = Ps[prow0][ks*8 + qc + 4];
            pf[3] = Ps[prow1][ks*8 + qc + 4];
            #pragma unroll
            for (int nt = 0; nt < 8; nt++) {
                unsigned b0 = Vs[ks*8 + qc    ][nt*8 + qr];
                unsigned b1 = Vs[ks*8 + qc + 4][nt*8 + qr];
                mma8(oacc[nt], pf, b0, b1);
            }
        }
        __syncwarp();
    }

    float inv0 = 1.0f / l0, inv1 = 1.0f / l1;
    #pragma unroll
    for (int nt = 0; nt < 8; nt++) {
        int col = h*64 + nt*8 + qc*2;
        if (v0) *(float2*)&g_o[((long)b*NTOK + r0)*DIM + col] =
            make_float2(oacc[nt].x * inv0, oacc[nt].y * inv0);
        if (v1) *(float2*)&g_o[((long)b*NTOK + r1)*DIM + col] =
            make_float2(oacc[nt].z * inv1, oacc[nt].w * inv1);
    }
}

// ---------------- LayerNorm on easy rows ----------------
__global__ void k_ln(const float* __restrict__ x, const float* __restrict__ g,
                     const float* __restrict__ be) {
    int b = blockIdx.y, m = blockIdx.x;
    if (m >= g_cntZ[b]) return;
    int tok = g_zidx[b*NTOK + m];
    const float* row = x + ((long)b*NTOK + tok)*DIM;
    int tid = threadIdx.x;
    float v[3];
    float s = 0.0f, s2 = 0.0f;
    #pragma unroll
    for (int i = 0; i < 3; i++) {
        v[i] = row[tid + i*256];
        s += v[i]; s2 += v[i]*v[i];
    }
    __shared__ float r0[256], r1[256];
    r0[tid] = s; r1[tid] = s2;
    __syncthreads();
    for (int off = 128; off; off >>= 1) {
        if (tid < off) { r0[tid] += r0[tid+off]; r1[tid] += r1[tid+off]; }
        __syncthreads();
    }
    float mu  = r0[0] * (1.0f/DIM);
    float var = r1[0] * (1.0f/DIM) - mu*mu;
    float rs  = rsqrtf(var + 1e-5f);
    float* outp = g_hln + ((long)b*NTOK + m)*DIM;
    #pragma unroll
    for (int i = 0; i < 3; i++) {
        int c = tid + i*256;
        outp[c] = (v[i] - mu) * rs * g[c] + be[c];
    }
}

// ---------------- masked mean pool ----------------
__global__ void k_pool() {
    int b = blockIdx.y;
    int c = blockIdx.x * 256 + threadIdx.x;
    int cz = g_cntZ[b];
    float s0 = 0, s1 = 0, s2 = 0, s3 = 0;
    int m = 0;
    for (; m + 4 <= cz; m += 4) {
        s0 += g_h2[((long)b*NTOK + m    )*DIM + c];
        s1 += g_h2[((long)b*NTOK + m + 1)*DIM + c];
        s2 += g_h2[((long)b*NTOK + m + 2)*DIM + c];
        s3 += g_h2[((long)b*NTOK + m + 3)*DIM + c];
    }
    for (; m < cz; m++) s0 += g_h2[((long)b*NTOK + m)*DIM + c];
    g_pool[b*DIM + c] = (s0 + s1 + s2 + s3) / fmaxf((float)cz, 1.0f);
}

// ---------------- ECA conv + sigmoid ----------------
__global__ void k_eca(const float* __restrict__ w) {
    int b = blockIdx.x, c = threadIdx.x;
    float g = 0.0f;
    #pragma unroll
    for (int tt = 0; tt < 5; tt++) {
        int cc = c + tt - 2;
        if (cc >= 0 && cc < DIM) g += w[tt] * g_pool[b*DIM + cc];
    }
    g_sig[b*DIM + c] = 1.0f / (1.0f + __expf(-g));
}

// ---------------- LTRM scatter ----------------
__global__ void k_ltrm(const float* __restrict__ x, float* __restrict__ out) {
    int b = blockIdx.y, m = blockIdx.x;
    if (m >= g_cntZ[b]) return;
    int tok = g_zidx[b*NTOK + m];
    long ro = ((long)b*NTOK + tok)*DIM;
    long ri = ((long)b*NTOK + m)*DIM;
    for (int c = threadIdx.x; c < DIM; c += 256)
        out[ro + c] = x[ro + c] + g_h2[ri + c] * g_sig[b*DIM + c];
}

// ---------------- launch ----------------
extern "C" void kernel_launch(void* const* d_in, const int* in_sizes, int n_in,
                              void* d_out, int out_size) {
    const float* x      = (const float*)d_in[0];
    const float* hint   = (const float*)d_in[1];
    const float* qkv_w  = (const float*)d_in[2];
    const float* qkv_b  = (const float*)d_in[3];
    const float* proj_w = (const float*)d_in[4];
    const float* proj_b = (const float*)d_in[5];
    const float* ln_g   = (const float*)d_in[6];
    const float* ln_b   = (const float*)d_in[7];
    const float* fc1_w  = (const float*)d_in[8];
    const float* fc1_b  = (const float*)d_in[9];
    const float* fc2_w  = (const float*)d_in[10];
    const float* fc2_b  = (const float*)d_in[11];
    const float* eca_w  = (const float*)d_in[12];
    float* out = (float*)d_out;

    k_reset   <<<1, 32>>>();
    k_edge    <<<BB*NTOK/8, 256>>>(hint);
    k_fallback<<<BB, 256>>>();
    k_compact <<<BB, 1024>>>();

    // edge path
    k_gemm<0><<<dim3(3*DIM/128, NTOK/128, BB), 256>>>(x, qkv_w, qkv_b, out);
    k_attn   <<<dim3((NTOK + 63)/64, HEADS, BB), 128>>>();
    k_gemm<1><<<dim3(DIM/128, NTOK/128, BB), 256>>>(x, proj_w, proj_b, out);

    // easy path (LTRM)
    k_ln     <<<dim3(NTOK, BB), 256>>>(x, ln_g, ln_b);
    k_gemm<2><<<dim3(HID/128, NTOK/128, BB), 256>>>(x, fc1_w, fc1_b, out);
    k_gemm<3><<<dim3(DIM/128, NTOK/128, BB), 256>>>(x, fc2_w, fc2_b, out);
    k_pool   <<<dim3(DIM/256, BB), 256>>>();
    k_eca    <<<BB, DIM>>>(eca_w);
    k_ltrm   <<<dim3(NTOK, BB), 256>>>(x, out);
}

// round 4
// speedup vs baseline: 3.4214x; 1.3339x over previous
#include <cuda_runtime.h>
#include <math.h>

#define BB     2
#define NTOK   4096
#define DIM    768
#define HEADS  12
#define HD     64
#define HID    1536
#define HINTR  1024

// ---------------- device scratch ----------------
__device__ int   g_edge[BB*NTOK];
__device__ int   g_raw[BB];
__device__ int   g_cntE[BB];
__device__ int   g_cntZ[BB];
__device__ int   g_eidx[BB*NTOK];
__device__ int   g_zidx[BB*NTOK];
__device__ float g_q  [(size_t)BB*HEADS*NTOK*HD];
__device__ float g_k  [(size_t)BB*HEADS*NTOK*HD];
__device__ float g_v  [(size_t)BB*HEADS*NTOK*HD];
__device__ float g_o  [(size_t)BB*NTOK*DIM];
__device__ float g_hln[(size_t)BB*NTOK*DIM];
__device__ float g_h1 [(size_t)BB*NTOK*HID];
__device__ float g_h2 [(size_t)BB*NTOK*DIM];
__device__ float g_poolp[BB*16*DIM];
__device__ float g_sig [BB*DIM];

// ---------------- mma + cp.async helpers ----------------
__device__ __forceinline__ void mma8(float4& d, const float* a, float b0f, float b1f) {
    unsigned a0 = __float_as_uint(a[0]), a1 = __float_as_uint(a[1]);
    unsigned a2 = __float_as_uint(a[2]), a3 = __float_as_uint(a[3]);
    unsigned b0 = __float_as_uint(b0f),  b1 = __float_as_uint(b1f);
    asm volatile(
        "mma.sync.aligned.m16n8k8.row.col.f32.tf32.tf32.f32 "
        "{%0,%1,%2,%3}, {%4,%5,%6,%7}, {%8,%9}, {%0,%1,%2,%3};\n"
        : "+f"(d.x), "+f"(d.y), "+f"(d.z), "+f"(d.w)
        : "r"(a0), "r"(a1), "r"(a2), "r"(a3), "r"(b0), "r"(b1));
}
__device__ __forceinline__ void cpa16(void* smem, const void* gmem) {
    unsigned s = (unsigned)__cvta_generic_to_shared(smem);
    asm volatile("cp.async.cg.shared.global [%0], [%1], 16;\n" :: "r"(s), "l"(gmem));
}
__device__ __forceinline__ void cpa16z(void* smem, const void* gmem, bool pred) {
    unsigned s = (unsigned)__cvta_generic_to_shared(smem);
    int sz = pred ? 16 : 0;
    asm volatile("cp.async.cg.shared.global [%0], [%1], 16, %2;\n" :: "r"(s), "l"(gmem), "r"(sz));
}
__device__ __forceinline__ void cpa_commit() { asm volatile("cp.async.commit_group;\n"); }
__device__ __forceinline__ void cpa_wait1()  { asm volatile("cp.async.wait_group 1;\n"); }

// ---------------- tiny setup kernels ----------------
__global__ void k_reset() {
    int i = threadIdx.x;
    if (i < BB) g_raw[i] = 0;
}

__global__ void k_edge(const float* __restrict__ hint) {
    int warp = threadIdx.x >> 5, lane = threadIdx.x & 31;
    int token = blockIdx.x * 8 + warp;
    int b = token / NTOK, t = token % NTOK;
    int ty = t >> 6, tx = t & 63;
    const float* base = hint + (size_t)b*HINTR*HINTR + (size_t)(ty*16)*HINTR + tx*16;
    int r = lane >> 1, half = lane & 1;
    const float4* p = (const float4*)(base + (size_t)r*HINTR + half*8);
    float4 a = p[0], c = p[1];
    float s = a.x+a.y+a.z+a.w + c.x+c.y+c.z+c.w;
    #pragma unroll
    for (int off = 16; off; off >>= 1) s += __shfl_down_sync(0xffffffffu, s, off);
    if (lane == 0) {
        float mean = s * (1.0f/256.0f);
        int e = (mean > 0.02f && mean < 0.98f) ? 1 : 0;
        g_edge[token] = e;
        if (e) atomicAdd(&g_raw[b], 1);
    }
}

__global__ void k_fallback() {
    int b = blockIdx.x;
    if (g_raw[b] >= 64) return;
    for (int t = threadIdx.x; t < NTOK; t += blockDim.x) g_edge[b*NTOK + t] = 1;
}

__global__ void k_compact() {
    int b = blockIdx.x, tid = threadIdx.x;
    int t0 = tid * 4;
    int f[4]; int e = 0;
    #pragma unroll
    for (int i = 0; i < 4; i++) { f[i] = g_edge[b*NTOK + t0 + i]; e += f[i]; }
    int lane = tid & 31, wid = tid >> 5;
    int v = e;
    #pragma unroll
    for (int off = 1; off < 32; off <<= 1) {
        int n = __shfl_up_sync(0xffffffffu, v, off);
        if (lane >= off) v += n;
    }
    __shared__ int wsum[32];
    if (lane == 31) wsum[wid] = v;
    __syncthreads();
    if (wid == 0) {
        int wv = wsum[lane];
        #pragma unroll
        for (int off = 1; off < 32; off <<= 1) {
            int n = __shfl_up_sync(0xffffffffu, wv, off);
            if (lane >= off) wv += n;
        }
        wsum[lane] = wv;
    }
    __syncthreads();
    int excl = v - e + (wid ? wsum[wid-1] : 0);
    int eoff = excl, zoff = t0 - excl;
    #pragma unroll
    for (int i = 0; i < 4; i++) {
        if (f[i]) g_eidx[b*NTOK + eoff++] = t0 + i;
        else      g_zidx[b*NTOK + zoff++] = t0 + i;
    }
    if (tid == 1023) { int tot = wsum[31]; g_cntE[b] = tot; g_cntZ[b] = NTOK - tot; }
}

// ---------------- pipelined tf32 MMA GEMM ----------------
// BM=128 BN=128 BK=16, 256 thr = 8 warps (2m x 4n), cp.async double buffer.
__device__ __forceinline__ float gelu_exact(float x) {
    return 0.5f * x * (1.0f + erff(x * 0.70710678118654752f));
}

template<int EPI>
__global__ void k_gemm(const float* __restrict__ xfull, const float* __restrict__ W,
                       const float* __restrict__ bias, float* __restrict__ dout)
{
    constexpr int K = (EPI == 3) ? HID : DIM;
    constexpr int N = (EPI == 0) ? 3*DIM : (EPI == 2 ? HID : DIM);
    constexpr int NT = K / 16;
    const int* cntp = (EPI >= 2) ? g_cntZ : g_cntE;

    int b = blockIdx.z;
    int M = cntp[b];
    int m0 = blockIdx.y * 128;
    if (m0 >= M) return;
    int n0 = blockIdx.x * 128;

    const float* A;
    if (EPI == 0)      A = xfull + (long)b*NTOK*DIM;
    else if (EPI == 1) A = g_o   + (long)b*NTOK*DIM;
    else if (EPI == 2) A = g_hln + (long)b*NTOK*DIM;
    else               A = g_h1  + (long)b*NTOK*HID;

    __shared__ float As[2][128][20];
    __shared__ float Bs[2][16][136];

    int tid = threadIdx.x;
    int w = tid >> 5, lane = tid & 31;
    int wm = (w >> 2) * 64, wn = (w & 3) * 32;
    int qr = lane >> 2, qc = lane & 3;

    int  mloc[2], kcid[2], krB[2], ncB[2];
    long arow[2];
    #pragma unroll
    for (int t = 0; t < 2; t++) {
        int task = tid + 256*t;
        mloc[t] = task >> 2; kcid[t] = task & 3;
        int gm = m0 + mloc[t];
        arow[t] = (gm < M) ? (long)((EPI == 0) ? g_eidx[b*NTOK + gm] : gm) * K : -1;
        krB[t] = task >> 5; ncB[t] = (task & 31) * 4;
    }

    auto issue = [&](int k0, int buf) {
        #pragma unroll
        for (int t = 0; t < 2; t++) {
            const float* asrc = (arow[t] >= 0) ? (A + arow[t] + k0 + kcid[t]*4) : A;
            cpa16z(&As[buf][mloc[t]][kcid[t]*4], asrc, arow[t] >= 0);
            cpa16(&Bs[buf][krB[t]][ncB[t]], W + (long)(k0 + krB[t])*N + n0 + ncB[t]);
        }
    };

    float4 acc[4][4];
    #pragma unroll
    for (int i = 0; i < 4; i++)
        #pragma unroll
        for (int j = 0; j < 4; j++) acc[i][j] = make_float4(0,0,0,0);

    issue(0, 0); cpa_commit();
    issue(16, 1); cpa_commit();

    #pragma unroll 1
    for (int it = 0; it < NT; it++) {
        cpa_wait1();
        __syncthreads();
        int buf = it & 1;
        #pragma unroll
        for (int kk = 0; kk < 16; kk += 8) {
            float af[4][4];
            #pragma unroll
            for (int mi = 0; mi < 4; mi++) {
                int mb = wm + mi*16;
                af[mi][0] = As[buf][mb + qr    ][kk + qc];
                af[mi][1] = As[buf][mb + qr + 8][kk + qc];
                af[mi][2] = As[buf][mb + qr    ][kk + qc + 4];
                af[mi][3] = As[buf][mb + qr + 8][kk + qc + 4];
            }
            #pragma unroll
            for (int ni = 0; ni < 4; ni++) {
                float b0 = Bs[buf][kk + qc    ][wn + ni*8 + qr];
                float b1 = Bs[buf][kk + qc + 4][wn + ni*8 + qr];
                #pragma unroll
                for (int mi = 0; mi < 4; mi++) mma8(acc[mi][ni], af[mi], b0, b1);
            }
        }
        __syncthreads();
        if (it + 2 < NT) issue((it + 2) * 16, buf);
        cpa_commit();
    }

    // epilogue
    #pragma unroll
    for (int mi = 0; mi < 4; mi++) {
        int rowA = m0 + wm + mi*16 + qr;
        int rowB = rowA + 8;
        #pragma unroll
        for (int ni = 0; ni < 4; ni++) {
            int col = n0 + wn + ni*8 + qc*2;
            float b0v = bias[col], b1v = bias[col+1];
            float vx = acc[mi][ni].x + b0v, vy = acc[mi][ni].y + b1v;
            float vz = acc[mi][ni].z + b0v, vw = acc[mi][ni].w + b1v;
            if (EPI == 0) {
                int part = col / DIM, cc = col - part*DIM;
                float* dst = (part == 0) ? g_q : (part == 1) ? g_k : g_v;
                int h = cc >> 6, d = cc & 63;
                long hb = ((long)b*HEADS + h)*NTOK;
                if (rowA < M) *(float2*)&dst[(hb + rowA)*HD + d] = make_float2(vx, vy);
                if (rowB < M) *(float2*)&dst[(hb + rowB)*HD + d] = make_float2(vz, vw);
            } else if (EPI == 1) {
                if (rowA < M) {
                    long o = ((long)b*NTOK + g_eidx[b*NTOK + rowA])*DIM + col;
                    *(float2*)&dout[o] = make_float2(vx + xfull[o], vy + xfull[o+1]);
                }
                if (rowB < M) {
                    long o = ((long)b*NTOK + g_eidx[b*NTOK + rowB])*DIM + col;
                    *(float2*)&dout[o] = make_float2(vz + xfull[o], vw + xfull[o+1]);
                }
            } else if (EPI == 2) {
                if (rowA < M) *(float2*)&g_h1[((long)b*NTOK + rowA)*HID + col] =
                    make_float2(gelu_exact(gelu_exact(vx)), gelu_exact(gelu_exact(vy)));
                if (rowB < M) *(float2*)&g_h1[((long)b*NTOK + rowB)*HID + col] =
                    make_float2(gelu_exact(gelu_exact(vz)), gelu_exact(gelu_exact(vw)));
            } else {
                if (rowA < M) *(float2*)&g_h2[((long)b*NTOK + rowA)*DIM + col] = make_float2(vx, vy);
                if (rowB < M) *(float2*)&g_h2[((long)b*NTOK + rowB)*DIM + col] = make_float2(vz, vw);
            }
        }
    }
}

// ---------------- pipelined tf32 flash attention ----------------
// 128 thr (4 warps), 64 queries/block, 32-key tiles, cp.async double buffer.
#define KT 32
__global__ void k_attn() {
    int b = blockIdx.z, h = blockIdx.y;
    int M = g_cntE[b];
    int m0 = blockIdx.x * 64;
    if (m0 >= M) return;
    int tid = threadIdx.x, w = tid >> 5, lane = tid & 31;
    int qr = lane >> 2, qc = lane & 3;
    long base = ((long)b*HEADS + h)*NTOK*HD;

    __shared__ float Ks[2][KT][68];
    __shared__ float Vs[2][KT][72];
    __shared__ float Ps[64][36];

    int r0 = m0 + w*16 + qr, r1 = r0 + 8;
    bool v0 = r0 < M, v1 = r1 < M;
    const float* q0p = g_q + base + (long)r0*HD;
    const float* q1p = g_q + base + (long)r1*HD;
    float qf[8][4];
    #pragma unroll
    for (int ks = 0; ks < 8; ks++) {
        int c = ks*8 + qc;
        qf[ks][0] = v0 ? q0p[c]   * 0.125f : 0.0f;
        qf[ks][1] = v1 ? q1p[c]   * 0.125f : 0.0f;
        qf[ks][2] = v0 ? q0p[c+4] * 0.125f : 0.0f;
        qf[ks][3] = v1 ? q1p[c+4] * 0.125f : 0.0f;
    }

    // KV tile loader: 512 16B-chunks per matrix per tile -> 4 tasks/thread each.
    auto issue = [&](int kb, int buf) {
        #pragma unroll
        for (int t = 0; t < 4; t++) {
            int task = tid + 128*t;        // 0..511
            int row  = task >> 4;          // 0..31
            int c4   = (task & 15) * 4;    // 0..60
            bool ok = (kb + row) < M;
            long off = base + (long)(kb + (ok ? row : 0))*HD + c4;
            cpa16z(&Ks[buf][row][c4], g_k + off, ok);
            cpa16z(&Vs[buf][row][c4], g_v + off, ok);
        }
    };

    float4 oacc[8];
    #pragma unroll
    for (int i = 0; i < 8; i++) oacc[i] = make_float4(0,0,0,0);
    float mx0 = -1e30f, mx1 = -1e30f, l0 = 0.0f, l1 = 0.0f;

    int ntiles = (M + KT - 1) / KT;
    issue(0, 0); cpa_commit();
    if (ntiles > 1) issue(KT, 1);
    cpa_commit();

    int prow0 = w*16 + qr, prow1 = prow0 + 8;
    #pragma unroll 1
    for (int kt = 0; kt < ntiles; kt++) {
        int kb = kt * KT;
        cpa_wait1();
        __syncthreads();
        int buf = kt & 1;

        // S = Q K^T : 4 n-tiles of 8 keys
        float4 s[4];
        #pragma unroll
        for (int nt = 0; nt < 4; nt++) s[nt] = make_float4(0,0,0,0);
        #pragma unroll
        for (int ks = 0; ks < 8; ks++) {
            #pragma unroll
            for (int nt = 0; nt < 4; nt++) {
                float b0 = Ks[buf][nt*8 + qr][ks*8 + qc];
                float b1 = Ks[buf][nt*8 + qr][ks*8 + qc + 4];
                mma8(s[nt], qf[ks], b0, b1);
            }
        }
        // mask + row max
        float t0 = -1e30f, t1 = -1e30f;
        #pragma unroll
        for (int nt = 0; nt < 4; nt++) {
            int c0 = kb + nt*8 + qc*2;
            if (c0     >= M) { s[nt].x = -1e30f; s[nt].z = -1e30f; }
            if (c0 + 1 >= M) { s[nt].y = -1e30f; s[nt].w = -1e30f; }
            t0 = fmaxf(t0, fmaxf(s[nt].x, s[nt].y));
            t1 = fmaxf(t1, fmaxf(s[nt].z, s[nt].w));
        }
        t0 = fmaxf(t0, __shfl_xor_sync(0xffffffffu, t0, 1));
        t0 = fmaxf(t0, __shfl_xor_sync(0xffffffffu, t0, 2));
        t1 = fmaxf(t1, __shfl_xor_sync(0xffffffffu, t1, 1));
        t1 = fmaxf(t1, __shfl_xor_sync(0xffffffffu, t1, 2));
        float nm0 = fmaxf(mx0, t0), nm1 = fmaxf(mx1, t1);
        float cr0 = __expf(mx0 - nm0), cr1 = __expf(mx1 - nm1);
        l0 *= cr0; l1 *= cr1;
        #pragma unroll
        for (int i = 0; i < 8; i++) {
            oacc[i].x *= cr0; oacc[i].y *= cr0;
            oacc[i].z *= cr1; oacc[i].w *= cr1;
        }
        mx0 = nm0; mx1 = nm1;

        float ps0 = 0.0f, ps1 = 0.0f;
        #pragma unroll
        for (int nt = 0; nt < 4; nt++) {
            float px = __expf(s[nt].x - mx0), py = __expf(s[nt].y - mx0);
            float pz = __expf(s[nt].z - mx1), pw = __expf(s[nt].w - mx1);
            ps0 += px + py; ps1 += pz + pw;
            int cc = nt*8 + qc*2;
            *(float2*)&Ps[prow0][cc] = make_float2(px, py);
            *(float2*)&Ps[prow1][cc] = make_float2(pz, pw);
        }
        ps0 += __shfl_xor_sync(0xffffffffu, ps0, 1);
        ps0 += __shfl_xor_sync(0xffffffffu, ps0, 2);
        ps1 += __shfl_xor_sync(0xffffffffu, ps1, 1);
        ps1 += __shfl_xor_sync(0xffffffffu, ps1, 2);
        l0 += ps0; l1 += ps1;
        __syncwarp();

        // O += P V : 4 k-steps, 8 n-tiles over HD
        #pragma unroll
        for (int ks = 0; ks < 4; ks++) {
            float pf[4];
            pf[0] = Ps[prow0][ks*8 + qc];
            pf[1] = Ps[prow1][ks*8 + qc];
            pf[2] = Ps[prow0][ks*8 + qc + 4];
            pf[3] = Ps[prow1][ks*8 + qc + 4];
            #pragma unroll
            for (int nt = 0; nt < 8; nt++) {
                float b0 = Vs[buf][ks*8 + qc    ][nt*8 + qr];
                float b1 = Vs[buf][ks*8 + qc + 4][nt*8 + qr];
                mma8(oacc[nt], pf, b0, b1);
            }
        }
        __syncthreads();
        if (kt + 2 < ntiles) issue(kb + 2*KT, buf);
        cpa_commit();
    }

    float inv0 = 1.0f / l0, inv1 = 1.0f / l1;
    #pragma unroll
    for (int nt = 0; nt < 8; nt++) {
        int col = h*64 + nt*8 + qc*2;
        if (v0) *(float2*)&g_o[((long)b*NTOK + r0)*DIM + col] =
            make_float2(oacc[nt].x * inv0, oacc[nt].y * inv0);
        if (v1) *(float2*)&g_o[((long)b*NTOK + r1)*DIM + col] =
            make_float2(oacc[nt].z * inv1, oacc[nt].w * inv1);
    }
}

// ---------------- LayerNorm on easy rows ----------------
__global__ void k_ln(const float* __restrict__ x, const float* __restrict__ g,
                     const float* __restrict__ be) {
    int b = blockIdx.y, m = blockIdx.x;
    if (m >= g_cntZ[b]) return;
    int tok = g_zidx[b*NTOK + m];
    const float* row = x + ((long)b*NTOK + tok)*DIM;
    int tid = threadIdx.x;
    float v[3];
    float s = 0.0f, s2 = 0.0f;
    #pragma unroll
    for (int i = 0; i < 3; i++) {
        v[i] = row[tid + i*256];
        s += v[i]; s2 += v[i]*v[i];
    }
    __shared__ float r0[256], r1[256];
    r0[tid] = s; r1[tid] = s2;
    __syncthreads();
    for (int off = 128; off; off >>= 1) {
        if (tid < off) { r0[tid] += r0[tid+off]; r1[tid] += r1[tid+off]; }
        __syncthreads();
    }
    float mu  = r0[0] * (1.0f/DIM);
    float var = r1[0] * (1.0f/DIM) - mu*mu;
    float rs  = rsqrtf(var + 1e-5f);
    float* outp = g_hln + ((long)b*NTOK + m)*DIM;
    #pragma unroll
    for (int i = 0; i < 3; i++) {
        int c = tid + i*256;
        outp[c] = (v[i] - mu) * rs * g[c] + be[c];
    }
}

// ---------------- 2-stage masked mean pool + fused ECA ----------------
__global__ void k_pool1() {
    int b = blockIdx.z, part = blockIdx.y;
    int c = blockIdx.x * 256 + threadIdx.x;
    int cz = g_cntZ[b];
    int chunk = (cz + 15) / 16;
    int mlo = part * chunk, mhi = min(mlo + chunk, cz);
    float s = 0.0f;
    for (int m = mlo; m < mhi; m++) s += g_h2[((long)b*NTOK + m)*DIM + c];
    g_poolp[(b*16 + part)*DIM + c] = s;
}

__global__ void k_pool2(const float* __restrict__ w) {
    int b = blockIdx.x, c = threadIdx.x;   // 768 threads
    __shared__ float pooled[DIM];
    float s = 0.0f;
    #pragma unroll
    for (int p = 0; p < 16; p++) s += g_poolp[(b*16 + p)*DIM + c];
    pooled[c] = s / fmaxf((float)g_cntZ[b], 1.0f);
    __syncthreads();
    float g = 0.0f;
    #pragma unroll
    for (int tt = 0; tt < 5; tt++) {
        int cc = c + tt - 2;
        if (cc >= 0 && cc < DIM) g += w[tt] * pooled[cc];
    }
    g_sig[b*DIM + c] = 1.0f / (1.0f + __expf(-g));
}

// ---------------- LTRM scatter ----------------
__global__ void k_ltrm(const float* __restrict__ x, float* __restrict__ out) {
    int b = blockIdx.y, m = blockIdx.x;
    if (m >= g_cntZ[b]) return;
    int tok = g_zidx[b*NTOK + m];
    long ro = ((long)b*NTOK + tok)*DIM;
    long ri = ((long)b*NTOK + m)*DIM;
    for (int c = threadIdx.x; c < DIM; c += 256)
        out[ro + c] = x[ro + c] + g_h2[ri + c] * g_sig[b*DIM + c];
}

// ---------------- launch ----------------
extern "C" void kernel_launch(void* const* d_in, const int* in_sizes, int n_in,
                              void* d_out, int out_size) {
    const float* x      = (const float*)d_in[0];
    const float* hint   = (const float*)d_in[1];
    const float* qkv_w  = (const float*)d_in[2];
    const float* qkv_b  = (const float*)d_in[3];
    const float* proj_w = (const float*)d_in[4];
    const float* proj_b = (const float*)d_in[5];
    const float* ln_g   = (const float*)d_in[6];
    const float* ln_b   = (const float*)d_in[7];
    const float* fc1_w  = (const float*)d_in[8];
    const float* fc1_b  = (const float*)d_in[9];
    const float* fc2_w  = (const float*)d_in[10];
    const float* fc2_b  = (const float*)d_in[11];
    const float* eca_w  = (const float*)d_in[12];
    float* out = (float*)d_out;

    k_reset   <<<1, 32>>>();
    k_edge    <<<BB*NTOK/8, 256>>>(hint);
    k_fallback<<<BB, 256>>>();
    k_compact <<<BB, 1024>>>();

    // edge path
    k_gemm<0><<<dim3(3*DIM/128, NTOK/128, BB), 256>>>(x, qkv_w, qkv_b, out);
    k_attn   <<<dim3((NTOK + 63)/64, HEADS, BB), 128>>>();
    k_gemm<1><<<dim3(DIM/128, NTOK/128, BB), 256>>>(x, proj_w, proj_b, out);

    // easy path (LTRM)
    k_ln     <<<dim3(NTOK, BB), 256>>>(x, ln_g, ln_b);
    k_gemm<2><<<dim3(HID/128, NTOK/128, BB), 256>>>(x, fc1_w, fc1_b, out);
    k_gemm<3><<<dim3(DIM/128, NTOK/128, BB), 256>>>(x, fc2_w, fc2_b, out);
    k_pool1  <<<dim3(DIM/256, 16, BB), 256>>>();
    k_pool2  <<<BB, DIM>>>(eca_w);
    k_ltrm   <<<dim3(NTOK, BB), 256>>>(x, out);
}

// round 5
// speedup vs baseline: 6.0812x; 1.7774x over previous
#include <cuda_runtime.h>
#include <cuda_fp16.h>
#include <math.h>

#define BB     2
#define NTOK   4096
#define DIM    768
#define HEADS  12
#define HD     64
#define HID    1536
#define HINTR  1024

// ---------------- device scratch ----------------
__device__ int    g_edge[BB*NTOK];
__device__ int    g_raw[BB];
__device__ int    g_cntE[BB];
__device__ int    g_cntZ[BB];
__device__ int    g_eidx[BB*NTOK];
__device__ int    g_zidx[BB*NTOK];
__device__ __half g_xh [(size_t)BB*NTOK*DIM];
__device__ __half g_wqkv[(size_t)DIM*3*DIM];
__device__ __half g_wproj[(size_t)DIM*DIM];
__device__ __half g_wfc1[(size_t)DIM*HID];
__device__ __half g_wfc2[(size_t)HID*DIM];
__device__ __half g_qh [(size_t)BB*HEADS*NTOK*HD];
__device__ __half g_kh [(size_t)BB*HEADS*NTOK*HD];
__device__ __half g_vh [(size_t)BB*HEADS*NTOK*HD];
__device__ __half g_oh [(size_t)BB*NTOK*DIM];
__device__ __half g_hln[(size_t)BB*NTOK*DIM];
__device__ __half g_h1 [(size_t)BB*NTOK*HID];
__device__ float  g_h2 [(size_t)BB*NTOK*DIM];
__device__ float  g_poolp[BB*16*DIM];
__device__ float  g_sig [BB*DIM];

// ---------------- asm helpers ----------------
__device__ __forceinline__ void mma16(float4& d, const unsigned* a, unsigned b0, unsigned b1) {
    asm volatile(
        "mma.sync.aligned.m16n8k16.row.col.f32.f16.f16.f32 "
        "{%0,%1,%2,%3}, {%4,%5,%6,%7}, {%8,%9}, {%0,%1,%2,%3};\n"
        : "+f"(d.x), "+f"(d.y), "+f"(d.z), "+f"(d.w)
        : "r"(a[0]), "r"(a[1]), "r"(a[2]), "r"(a[3]), "r"(b0), "r"(b1));
}
__device__ __forceinline__ void ldsm4(unsigned* r, const void* p) {
    unsigned a = (unsigned)__cvta_generic_to_shared(p);
    asm volatile("ldmatrix.sync.aligned.m8n8.x4.shared.b16 {%0,%1,%2,%3}, [%4];\n"
        : "=r"(r[0]), "=r"(r[1]), "=r"(r[2]), "=r"(r[3]) : "r"(a));
}
__device__ __forceinline__ void ldsm4t(unsigned* r, const void* p) {
    unsigned a = (unsigned)__cvta_generic_to_shared(p);
    asm volatile("ldmatrix.sync.aligned.m8n8.x4.trans.shared.b16 {%0,%1,%2,%3}, [%4];\n"
        : "=r"(r[0]), "=r"(r[1]), "=r"(r[2]), "=r"(r[3]) : "r"(a));
}
__device__ __forceinline__ void cpa16(void* smem, const void* gmem) {
    unsigned s = (unsigned)__cvta_generic_to_shared(smem);
    asm volatile("cp.async.cg.shared.global [%0], [%1], 16;\n" :: "r"(s), "l"(gmem));
}
__device__ __forceinline__ void cpa16z(void* smem, const void* gmem, bool pred) {
    unsigned s = (unsigned)__cvta_generic_to_shared(smem);
    int sz = pred ? 16 : 0;
    asm volatile("cp.async.cg.shared.global [%0], [%1], 16, %2;\n" :: "r"(s), "l"(gmem), "r"(sz));
}
__device__ __forceinline__ void cpa_commit() { asm volatile("cp.async.commit_group;\n"); }
__device__ __forceinline__ void cpa_wait1()  { asm volatile("cp.async.wait_group 1;\n"); }
__device__ __forceinline__ unsigned h2u(__half2 h) { return *(unsigned*)&h; }

// ---------------- fp32 -> fp16 convert (8 elems/thread) ----------------
__global__ void k_cvt(const float* __restrict__ src, __half* __restrict__ dst, int n) {
    int i = (blockIdx.x * 256 + threadIdx.x) * 8;
    if (i >= n) return;
    float4 f0 = *(const float4*)(src + i);
    float4 f1 = *(const float4*)(src + i + 4);
    __half2 h[4] = { __floats2half2_rn(f0.x, f0.y), __floats2half2_rn(f0.z, f0.w),
                     __floats2half2_rn(f1.x, f1.y), __floats2half2_rn(f1.z, f1.w) };
    *(uint4*)(dst + i) = *(uint4*)h;
}

// ---------------- tiny setup kernels ----------------
__global__ void k_reset() {
    int i = threadIdx.x;
    if (i < BB) g_raw[i] = 0;
}

__global__ void k_edge(const float* __restrict__ hint) {
    int warp = threadIdx.x >> 5, lane = threadIdx.x & 31;
    int token = blockIdx.x * 8 + warp;
    int b = token / NTOK, t = token % NTOK;
    int ty = t >> 6, tx = t & 63;
    const float* base = hint + (size_t)b*HINTR*HINTR + (size_t)(ty*16)*HINTR + tx*16;
    int r = lane >> 1, half = lane & 1;
    const float4* p = (const float4*)(base + (size_t)r*HINTR + half*8);
    float4 a = p[0], c = p[1];
    float s = a.x+a.y+a.z+a.w + c.x+c.y+c.z+c.w;
    #pragma unroll
    for (int off = 16; off; off >>= 1) s += __shfl_down_sync(0xffffffffu, s, off);
    if (lane == 0) {
        float mean = s * (1.0f/256.0f);
        int e = (mean > 0.02f && mean < 0.98f) ? 1 : 0;
        g_edge[token] = e;
        if (e) atomicAdd(&g_raw[b], 1);
    }
}

__global__ void k_fallback() {
    int b = blockIdx.x;
    if (g_raw[b] >= 64) return;
    for (int t = threadIdx.x; t < NTOK; t += blockDim.x) g_edge[b*NTOK + t] = 1;
}

__global__ void k_compact() {
    int b = blockIdx.x, tid = threadIdx.x;
    int t0 = tid * 4;
    int f[4]; int e = 0;
    #pragma unroll
    for (int i = 0; i < 4; i++) { f[i] = g_edge[b*NTOK + t0 + i]; e += f[i]; }
    int lane = tid & 31, wid = tid >> 5;
    int v = e;
    #pragma unroll
    for (int off = 1; off < 32; off <<= 1) {
        int n = __shfl_up_sync(0xffffffffu, v, off);
        if (lane >= off) v += n;
    }
    __shared__ int wsum[32];
    if (lane == 31) wsum[wid] = v;
    __syncthreads();
    if (wid == 0) {
        int wv = wsum[lane];
        #pragma unroll
        for (int off = 1; off < 32; off <<= 1) {
            int n = __shfl_up_sync(0xffffffffu, wv, off);
            if (lane >= off) wv += n;
        }
        wsum[lane] = wv;
    }
    __syncthreads();
    int excl = v - e + (wid ? wsum[wid-1] : 0);
    int eoff = excl, zoff = t0 - excl;
    #pragma unroll
    for (int i = 0; i < 4; i++) {
        if (f[i]) g_eidx[b*NTOK + eoff++] = t0 + i;
        else      g_zidx[b*NTOK + zoff++] = t0 + i;
    }
    if (tid == 1023) { int tot = wsum[31]; g_cntE[b] = tot; g_cntZ[b] = NTOK - tot; }
}

// ---------------- fp16 MMA GEMM: BM=128 BN=128 BK=32, cp.async x2, ldmatrix ----------------
__device__ __forceinline__ float gelu_exact(float x) {
    return 0.5f * x * (1.0f + erff(x * 0.70710678118654752f));
}

template<int EPI>
__global__ void __launch_bounds__(256)
k_gemm(const float* __restrict__ xfull, const __half* __restrict__ A,
       const __half* __restrict__ W, const float* __restrict__ bias,
       float* __restrict__ dout)
{
    constexpr int K = (EPI == 3) ? HID : DIM;
    constexpr int N = (EPI == 0) ? 3*DIM : (EPI == 2 ? HID : DIM);
    constexpr int NT = K / 32;
    const int* cntp = (EPI >= 2) ? g_cntZ : g_cntE;

    int b = blockIdx.z;
    int M = cntp[b];
    int m0 = blockIdx.y * 128;
    if (m0 >= M) return;
    int n0 = blockIdx.x * 128;
    const __half* Ab = A + (long)b * NTOK * K;

    __shared__ __half As[2][128][40];
    __shared__ __half Bs[2][32][136];

    int tid = threadIdx.x;
    int w = tid >> 5, lane = tid & 31;
    int wm = (w >> 2) * 64, wn = (w & 3) * 32;
    int qr = lane >> 2, qc = lane & 3;

    // A tasks: 512 chunks (128 rows x 4); B tasks: 512 chunks (32 rows x 16)
    int  mA[2], cA[2], krB[2], cB[2];
    long arow[2];
    #pragma unroll
    for (int t = 0; t < 2; t++) {
        int task = tid + 256*t;
        mA[t] = task >> 2; cA[t] = (task & 3) * 8;
        int gm = m0 + mA[t];
        arow[t] = (gm < M) ? (long)((EPI == 0) ? g_eidx[b*NTOK + gm] : gm) * K : -1;
        krB[t] = task >> 4; cB[t] = (task & 15) * 8;
    }

    auto issue = [&](int k0, int buf) {
        #pragma unroll
        for (int t = 0; t < 2; t++) {
            const __half* asrc = (arow[t] >= 0) ? (Ab + arow[t] + k0 + cA[t]) : Ab;
            cpa16z(&As[buf][mA[t]][cA[t]], asrc, arow[t] >= 0);
            cpa16(&Bs[buf][krB[t]][cB[t]], W + (long)(k0 + krB[t])*N + n0 + cB[t]);
        }
    };

    float4 acc[4][4];
    #pragma unroll
    for (int i = 0; i < 4; i++)
        #pragma unroll
        for (int j = 0; j < 4; j++) acc[i][j] = make_float4(0,0,0,0);

    issue(0, 0); cpa_commit();
    issue(32, 1); cpa_commit();

    #pragma unroll 1
    for (int it = 0; it < NT; it++) {
        cpa_wait1();
        __syncthreads();
        int buf = it & 1;
        // B frags: x4.trans covers k0-31 for one 8-col n tile
        unsigned bfr[4][4];
        #pragma unroll
        for (int ni = 0; ni < 4; ni++)
            ldsm4t(bfr[ni], &Bs[buf][lane][wn + ni*8]);
        #pragma unroll
        for (int ks = 0; ks < 2; ks++) {
            unsigned afr[4][4];
            #pragma unroll
            for (int mi = 0; mi < 4; mi++)
                ldsm4(afr[mi], &As[buf][wm + mi*16 + (lane & 15)][ks*16 + (lane >> 4)*8]);
            #pragma unroll
            for (int ni = 0; ni < 4; ni++)
                #pragma unroll
                for (int mi = 0; mi < 4; mi++)
                    mma16(acc[mi][ni], afr[mi], bfr[ni][ks*2], bfr[ni][ks*2+1]);
        }
        __syncthreads();
        if (it + 2 < NT) issue((it + 2) * 32, buf);
        cpa_commit();
    }

    // epilogue
    #pragma unroll
    for (int mi = 0; mi < 4; mi++) {
        int rowA = m0 + wm + mi*16 + qr;
        int rowB = rowA + 8;
        #pragma unroll
        for (int ni = 0; ni < 4; ni++) {
            int col = n0 + wn + ni*8 + qc*2;
            float b0v = bias[col], b1v = bias[col+1];
            float vx = acc[mi][ni].x + b0v, vy = acc[mi][ni].y + b1v;
            float vz = acc[mi][ni].z + b0v, vw = acc[mi][ni].w + b1v;
            if (EPI == 0) {
                int part = col / DIM, cc = col - part*DIM;
                __half* dst = (part == 0) ? g_qh : (part == 1) ? g_kh : g_vh;
                int h = cc >> 6, d = cc & 63;
                long hb = ((long)b*HEADS + h)*NTOK;
                if (rowA < M) *(__half2*)&dst[(hb + rowA)*HD + d] = __floats2half2_rn(vx, vy);
                if (rowB < M) *(__half2*)&dst[(hb + rowB)*HD + d] = __floats2half2_rn(vz, vw);
            } else if (EPI == 1) {
                if (rowA < M) {
                    long o = ((long)b*NTOK + g_eidx[b*NTOK + rowA])*DIM + col;
                    *(float2*)&dout[o] = make_float2(vx + xfull[o], vy + xfull[o+1]);
                }
                if (rowB < M) {
                    long o = ((long)b*NTOK + g_eidx[b*NTOK + rowB])*DIM + col;
                    *(float2*)&dout[o] = make_float2(vz + xfull[o], vw + xfull[o+1]);
                }
            } else if (EPI == 2) {
                if (rowA < M) *(__half2*)&g_h1[((long)b*NTOK + rowA)*HID + col] =
                    __floats2half2_rn(gelu_exact(gelu_exact(vx)), gelu_exact(gelu_exact(vy)));
                if (rowB < M) *(__half2*)&g_h1[((long)b*NTOK + rowB)*HID + col] =
                    __floats2half2_rn(gelu_exact(gelu_exact(vz)), gelu_exact(gelu_exact(vw)));
            } else {
                if (rowA < M) *(float2*)&g_h2[((long)b*NTOK + rowA)*DIM + col] = make_float2(vx, vy);
                if (rowB < M) *(float2*)&g_h2[((long)b*NTOK + rowB)*DIM + col] = make_float2(vz, vw);
            }
        }
    }
}

// ---------------- fp16 flash attention: 4 warps, 64 q/block, 32-key tiles ----------------
#define KT 32
__global__ void __launch_bounds__(128) k_attn() {
    int b = blockIdx.z, h = blockIdx.y;
    int M = g_cntE[b];
    int m0 = blockIdx.x * 64;
    if (m0 >= M) return;
    int tid = threadIdx.x, w = tid >> 5, lane = tid & 31;
    int qr = lane >> 2, qc = lane & 3;
    long base = ((long)b*HEADS + h)*NTOK*HD;

    __shared__ __half Ks[2][KT][72];
    __shared__ __half Vs[2][KT][72];

    int r0 = m0 + w*16 + qr, r1 = r0 + 8;
    bool v0 = r0 < M, v1 = r1 < M;
    const __half* q0p = g_qh + base + (long)r0*HD;
    const __half* q1p = g_qh + base + (long)r1*HD;
    unsigned qf[4][4];
    #pragma unroll
    for (int ks = 0; ks < 4; ks++) {
        int c = ks*16 + qc*2;
        qf[ks][0] = v0 ? *(const unsigned*)&q0p[c]   : 0u;
        qf[ks][1] = v1 ? *(const unsigned*)&q1p[c]   : 0u;
        qf[ks][2] = v0 ? *(const unsigned*)&q0p[c+8] : 0u;
        qf[ks][3] = v1 ? *(const unsigned*)&q1p[c+8] : 0u;
    }

    // loader: K 256 chunks + V 256 chunks; 4 tasks/thread
    auto issue = [&](int kb, int buf) {
        #pragma unroll
        for (int t = 0; t < 4; t++) {
            int task = tid + 128*t;            // 0..511
            int mat  = task >> 8;              // 0 = K, 1 = V
            int t2   = task & 255;
            int row  = t2 >> 3;
            int c8   = (t2 & 7) * 8;
            bool ok = (kb + row) < M;
            const __half* src = (mat ? g_vh : g_kh) + base + (long)(kb + (ok ? row : 0))*HD + c8;
            if (mat) cpa16z(&Vs[buf][row][c8], src, ok);
            else     cpa16z(&Ks[buf][row][c8], src, ok);
        }
    };

    float4 oacc[8];
    #pragma unroll
    for (int i = 0; i < 8; i++) oacc[i] = make_float4(0,0,0,0);
    float mx0 = -1e30f, mx1 = -1e30f, l0 = 0.0f, l1 = 0.0f;

    int ntiles = (M + KT - 1) / KT;
    issue(0, 0); cpa_commit();
    if (ntiles > 1) issue(KT, 1);
    cpa_commit();

    #pragma unroll 1
    for (int kt = 0; kt < ntiles; kt++) {
        int kb = kt * KT;
        cpa_wait1();
        __syncthreads();
        int buf = kt & 1;

        // S = Q K^T
        float4 s[4];
        #pragma unroll
        for (int nt = 0; nt < 4; nt++) s[nt] = make_float4(0,0,0,0);
        #pragma unroll
        for (int dh = 0; dh < 2; dh++) {
            unsigned kf[4][4];
            #pragma unroll
            for (int nt = 0; nt < 4; nt++)
                ldsm4(kf[nt], &Ks[buf][nt*8 + (lane & 7)][(lane >> 3)*8 + dh*32]);
            #pragma unroll
            for (int ksd = 0; ksd < 2; ksd++)
                #pragma unroll
                for (int nt = 0; nt < 4; nt++)
                    mma16(s[nt], qf[dh*2 + ksd], kf[nt][ksd*2], kf[nt][ksd*2+1]);
        }
        // scale, mask, row max
        float t0 = -1e30f, t1 = -1e30f;
        #pragma unroll
        for (int nt = 0; nt < 4; nt++) {
            s[nt].x *= 0.125f; s[nt].y *= 0.125f; s[nt].z *= 0.125f; s[nt].w *= 0.125f;
            int c0 = kb + nt*8 + qc*2;
            if (c0     >= M) { s[nt].x = -1e30f; s[nt].z = -1e30f; }
            if (c0 + 1 >= M) { s[nt].y = -1e30f; s[nt].w = -1e30f; }
            t0 = fmaxf(t0, fmaxf(s[nt].x, s[nt].y));
            t1 = fmaxf(t1, fmaxf(s[nt].z, s[nt].w));
        }
        t0 = fmaxf(t0, __shfl_xor_sync(0xffffffffu, t0, 1));
        t0 = fmaxf(t0, __shfl_xor_sync(0xffffffffu, t0, 2));
        t1 = fmaxf(t1, __shfl_xor_sync(0xffffffffu, t1, 1));
        t1 = fmaxf(t1, __shfl_xor_sync(0xffffffffu, t1, 2));
        float nm0 = fmaxf(mx0, t0), nm1 = fmaxf(mx1, t1);
        float cr0 = __expf(mx0 - nm0), cr1 = __expf(mx1 - nm1);
        l0 *= cr0; l1 *= cr1;
        #pragma unroll
        for (int i = 0; i < 8; i++) {
            oacc[i].x *= cr0; oacc[i].y *= cr0;
            oacc[i].z *= cr1; oacc[i].w *= cr1;
        }
        mx0 = nm0; mx1 = nm1;

        // exp -> fp16 A-frags for PV (directly from registers)
        float ps0 = 0.0f, ps1 = 0.0f;
        unsigned pa[2][4];
        #pragma unroll
        for (int nt = 0; nt < 4; nt++) {
            float px = __expf(s[nt].x - mx0), py = __expf(s[nt].y - mx0);
            float pz = __expf(s[nt].z - mx1), pw = __expf(s[nt].w - mx1);
            ps0 += px + py; ps1 += pz + pw;
            int ks = nt >> 1, hi = (nt & 1) * 2;
            pa[ks][hi]     = h2u(__floats2half2_rn(px, py));
            pa[ks][hi + 1] = h2u(__floats2half2_rn(pz, pw));
        }
        ps0 += __shfl_xor_sync(0xffffffffu, ps0, 1);
        ps0 += __shfl_xor_sync(0xffffffffu, ps0, 2);
        ps1 += __shfl_xor_sync(0xffffffffu, ps1, 1);
        ps1 += __shfl_xor_sync(0xffffffffu, ps1, 2);
        l0 += ps0; l1 += ps1;

        // O += P V
        #pragma unroll
        for (int ks = 0; ks < 2; ks++) {
            unsigned vf[4][4];
            #pragma unroll
            for (int dp = 0; dp < 4; dp++)
                ldsm4t(vf[dp], &Vs[buf][16*ks + ((lane >> 3) & 1)*8 + (lane & 7)]
                                  [dp*16 + (lane >> 4)*8]);
            #pragma unroll
            for (int nt = 0; nt < 8; nt++)
                mma16(oacc[nt], pa[ks], vf[nt >> 1][(nt & 1)*2], vf[nt >> 1][(nt & 1)*2 + 1]);
        }
        __syncthreads();
        if (kt + 2 < ntiles) issue(kb + 2*KT, buf);
        cpa_commit();
    }

    float inv0 = 1.0f / l0, inv1 = 1.0f / l1;
    #pragma unroll
    for (int nt = 0; nt < 8; nt++) {
        int col = h*64 + nt*8 + qc*2;
        if (v0) *(__half2*)&g_oh[((long)b*NTOK + r0)*DIM + col] =
            __floats2half2_rn(oacc[nt].x * inv0, oacc[nt].y * inv0);
        if (v1) *(__half2*)&g_oh[((long)b*NTOK + r1)*DIM + col] =
            __floats2half2_rn(oacc[nt].z * inv1, oacc[nt].w * inv1);
    }
}

// ---------------- LayerNorm on easy rows (fp16 out) ----------------
__global__ void k_ln(const float* __restrict__ x, const float* __restrict__ g,
                     const float* __restrict__ be) {
    int b = blockIdx.y, m = blockIdx.x;
    if (m >= g_cntZ[b]) return;
    int tok = g_zidx[b*NTOK + m];
    const float* row = x + ((long)b*NTOK + tok)*DIM;
    int tid = threadIdx.x;
    float v[3];
    float s = 0.0f, s2 = 0.0f;
    #pragma unroll
    for (int i = 0; i < 3; i++) {
        v[i] = row[tid + i*256];
        s += v[i]; s2 += v[i]*v[i];
    }
    __shared__ float r0[256], r1[256];
    r0[tid] = s; r1[tid] = s2;
    __syncthreads();
    for (int off = 128; off; off >>= 1) {
        if (tid < off) { r0[tid] += r0[tid+off]; r1[tid] += r1[tid+off]; }
        __syncthreads();
    }
    float mu  = r0[0] * (1.0f/DIM);
    float var = r1[0] * (1.0f/DIM) - mu*mu;
    float rs  = rsqrtf(var + 1e-5f);
    __half* outp = g_hln + ((long)b*NTOK + m)*DIM;
    #pragma unroll
    for (int i = 0; i < 3; i++) {
        int c = tid + i*256;
        outp[c] = __float2half_rn((v[i] - mu) * rs * g[c] + be[c]);
    }
}

// ---------------- 2-stage masked mean pool + fused ECA ----------------
__global__ void k_pool1() {
    int b = blockIdx.z, part = blockIdx.y;
    int c = blockIdx.x * 256 + threadIdx.x;
    int cz = g_cntZ[b];
    int chunk = (cz + 15) / 16;
    int mlo = part * chunk, mhi = min(mlo + chunk, cz);
    float s = 0.0f;
    for (int m = mlo; m < mhi; m++) s += g_h2[((long)b*NTOK + m)*DIM + c];
    g_poolp[(b*16 + part)*DIM + c] = s;
}

__global__ void k_pool2(const float* __restrict__ w) {
    int b = blockIdx.x, c = threadIdx.x;
    __shared__ float pooled[DIM];
    float s = 0.0f;
    #pragma unroll
    for (int p = 0; p < 16; p++) s += g_poolp[(b*16 + p)*DIM + c];
    pooled[c] = s / fmaxf((float)g_cntZ[b], 1.0f);
    __syncthreads();
    float g = 0.0f;
    #pragma unroll
    for (int tt = 0; tt < 5; tt++) {
        int cc = c + tt - 2;
        if (cc >= 0 && cc < DIM) g += w[tt] * pooled[cc];
    }
    g_sig[b*DIM + c] = 1.0f / (1.0f + __expf(-g));
}

// ---------------- LTRM scatter ----------------
__global__ void k_ltrm(const float* __restrict__ x, float* __restrict__ out) {
    int b = blockIdx.y, m = blockIdx.x;
    if (m >= g_cntZ[b]) return;
    int tok = g_zidx[b*NTOK + m];
    long ro = ((long)b*NTOK + tok)*DIM;
    long ri = ((long)b*NTOK + m)*DIM;
    for (int c = threadIdx.x; c < DIM; c += 256)
        out[ro + c] = x[ro + c] + g_h2[ri + c] * g_sig[b*DIM + c];
}

// ---------------- launch ----------------
extern "C" void kernel_launch(void* const* d_in, const int* in_sizes, int n_in,
                              void* d_out, int out_size) {
    const float* x      = (const float*)d_in[0];
    const float* hint   = (const float*)d_in[1];
    const float* qkv_w  = (const float*)d_in[2];
    const float* qkv_b  = (const float*)d_in[3];
    const float* proj_w = (const float*)d_in[4];
    const float* proj_b = (const float*)d_in[5];
    const float* ln_g   = (const float*)d_in[6];
    const float* ln_b   = (const float*)d_in[7];
    const float* fc1_w  = (const float*)d_in[8];
    const float* fc1_b  = (const float*)d_in[9];
    const float* fc2_w  = (const float*)d_in[10];
    const float* fc2_b  = (const float*)d_in[11];
    const float* eca_w  = (const float*)d_in[12];
    float* out = (float*)d_out;

    __half *d_xh, *d_wqkv, *d_wproj, *d_wfc1, *d_wfc2;
    cudaGetSymbolAddress((void**)&d_xh,   g_xh);
    cudaGetSymbolAddress((void**)&d_wqkv, g_wqkv);
    cudaGetSymbolAddress((void**)&d_wproj,g_wproj);
    cudaGetSymbolAddress((void**)&d_wfc1, g_wfc1);
    cudaGetSymbolAddress((void**)&d_wfc2, g_wfc2);
    __half *d_oh, *d_hln, *d_h1;
    cudaGetSymbolAddress((void**)&d_oh,  g_oh);
    cudaGetSymbolAddress((void**)&d_hln, g_hln);
    cudaGetSymbolAddress((void**)&d_h1,  g_h1);

    k_reset   <<<1, 32>>>();
    k_edge    <<<BB*NTOK/8, 256>>>(hint);
    k_fallback<<<BB, 256>>>();
    k_compact <<<BB, 1024>>>();

    // fp16 copies
    k_cvt<<<BB*NTOK*DIM/2048, 256>>>(x,      d_xh,   BB*NTOK*DIM);
    k_cvt<<<DIM*3*DIM/2048,  256>>>(qkv_w,  d_wqkv, DIM*3*DIM);
    k_cvt<<<DIM*DIM/2048,    256>>>(proj_w, d_wproj,DIM*DIM);
    k_cvt<<<DIM*HID/2048,    256>>>(fc1_w,  d_wfc1, DIM*HID);
    k_cvt<<<HID*DIM/2048,    256>>>(fc2_w,  d_wfc2, HID*DIM);

    // edge path
    k_gemm<0><<<dim3(3*DIM/128, NTOK/128, BB), 256>>>(x, d_xh, d_wqkv, qkv_b, out);
    k_attn   <<<dim3((NTOK + 63)/64, HEADS, BB), 128>>>();
    k_gemm<1><<<dim3(DIM/128, NTOK/128, BB), 256>>>(x, d_oh, d_wproj, proj_b, out);

    // easy path (LTRM)
    k_ln     <<<dim3(NTOK, BB), 256>>>(x, ln_g, ln_b);
    k_gemm<2><<<dim3(HID/128, NTOK/128, BB), 256>>>(x, d_hln, d_wfc1, fc1_b, out);
    k_gemm<3><<<dim3(DIM/128, NTOK/128, BB), 256>>>(x, d_h1, d_wfc2, fc2_b, out);
    k_pool1  <<<dim3(DIM/256, 16, BB), 256>>>();
    k_pool2  <<<BB, DIM>>>(eca_w);
    k_ltrm   <<<dim3(NTOK, BB), 256>>>(x, out);
}

// round 6
// speedup vs baseline: 7.1259x; 1.1718x over previous
#include <cuda_runtime.h>
#include <cuda_fp16.h>
#include <math.h>

#define BB     2
#define NTOK   4096
#define DIM    768
#define HEADS  12
#define HD     64
#define HID    1536
#define HINTR  1024

// ---------------- device scratch ----------------
__device__ int    g_edge[BB*NTOK];
__device__ int    g_raw[BB];
__device__ int    g_cntE[BB];
__device__ int    g_cntZ[BB];
__device__ int    g_eidx[BB*NTOK];
__device__ int    g_zidx[BB*NTOK];
__device__ __half g_xh [(size_t)BB*NTOK*DIM];
__device__ __half g_wqkv[(size_t)DIM*3*DIM];
__device__ __half g_wproj[(size_t)DIM*DIM];
__device__ __half g_wfc1[(size_t)DIM*HID];
__device__ __half g_wfc2[(size_t)HID*DIM];
__device__ __half g_qh [(size_t)BB*HEADS*NTOK*HD];
__device__ __half g_kh [(size_t)BB*HEADS*NTOK*HD];
__device__ __half g_vh [(size_t)BB*HEADS*NTOK*HD];
__device__ __half g_oh [(size_t)BB*NTOK*DIM];
__device__ __half g_hln[(size_t)BB*NTOK*DIM];
__device__ __half g_h1 [(size_t)BB*NTOK*HID];
__device__ float  g_h2 [(size_t)BB*NTOK*DIM];
__device__ float  g_poolp[BB*16*DIM];
__device__ float  g_sig [BB*DIM];

// ---------------- asm helpers ----------------
__device__ __forceinline__ void mma16(float4& d, const unsigned* a, unsigned b0, unsigned b1) {
    asm volatile(
        "mma.sync.aligned.m16n8k16.row.col.f32.f16.f16.f32 "
        "{%0,%1,%2,%3}, {%4,%5,%6,%7}, {%8,%9}, {%0,%1,%2,%3};\n"
        : "+f"(d.x), "+f"(d.y), "+f"(d.z), "+f"(d.w)
        : "r"(a[0]), "r"(a[1]), "r"(a[2]), "r"(a[3]), "r"(b0), "r"(b1));
}
__device__ __forceinline__ void ldsm4(unsigned* r, const void* p) {
    unsigned a = (unsigned)__cvta_generic_to_shared(p);
    asm volatile("ldmatrix.sync.aligned.m8n8.x4.shared.b16 {%0,%1,%2,%3}, [%4];\n"
        : "=r"(r[0]), "=r"(r[1]), "=r"(r[2]), "=r"(r[3]) : "r"(a));
}
__device__ __forceinline__ void ldsm4t(unsigned* r, const void* p) {
    unsigned a = (unsigned)__cvta_generic_to_shared(p);
    asm volatile("ldmatrix.sync.aligned.m8n8.x4.trans.shared.b16 {%0,%1,%2,%3}, [%4];\n"
        : "=r"(r[0]), "=r"(r[1]), "=r"(r[2]), "=r"(r[3]) : "r"(a));
}
__device__ __forceinline__ void cpa16(void* smem, const void* gmem) {
    unsigned s = (unsigned)__cvta_generic_to_shared(smem);
    asm volatile("cp.async.cg.shared.global [%0], [%1], 16;\n" :: "r"(s), "l"(gmem));
}
__device__ __forceinline__ void cpa16z(void* smem, const void* gmem, bool pred) {
    unsigned s = (unsigned)__cvta_generic_to_shared(smem);
    int sz = pred ? 16 : 0;
    asm volatile("cp.async.cg.shared.global [%0], [%1], 16, %2;\n" :: "r"(s), "l"(gmem), "r"(sz));
}
__device__ __forceinline__ void cpa_commit() { asm volatile("cp.async.commit_group;\n"); }
__device__ __forceinline__ void cpa_wait1()  { asm volatile("cp.async.wait_group 1;\n"); }
__device__ __forceinline__ unsigned h2u(__half2 h) { return *(unsigned*)&h; }
__device__ __forceinline__ float ex2(float x) {
    float y; asm("ex2.approx.ftz.f32 %0, %1;" : "=f"(y) : "f"(x)); return y;
}

// ---------------- fp32 -> fp16 convert ----------------
__global__ void k_cvt(const float* __restrict__ src, __half* __restrict__ dst, int n) {
    int i = (blockIdx.x * 256 + threadIdx.x) * 8;
    if (i >= n) return;
    float4 f0 = *(const float4*)(src + i);
    float4 f1 = *(const float4*)(src + i + 4);
    __half2 h[4] = { __floats2half2_rn(f0.x, f0.y), __floats2half2_rn(f0.z, f0.w),
                     __floats2half2_rn(f1.x, f1.y), __floats2half2_rn(f1.z, f1.w) };
    *(uint4*)(dst + i) = *(uint4*)h;
}

// ---------------- tiny setup kernels ----------------
__global__ void k_reset() {
    int i = threadIdx.x;
    if (i < BB) g_raw[i] = 0;
}

__global__ void k_edge(const float* __restrict__ hint) {
    int warp = threadIdx.x >> 5, lane = threadIdx.x & 31;
    int token = blockIdx.x * 8 + warp;
    int b = token / NTOK, t = token % NTOK;
    int ty = t >> 6, tx = t & 63;
    const float* base = hint + (size_t)b*HINTR*HINTR + (size_t)(ty*16)*HINTR + tx*16;
    int r = lane >> 1, half = lane & 1;
    const float4* p = (const float4*)(base + (size_t)r*HINTR + half*8);
    float4 a = p[0], c = p[1];
    float s = a.x+a.y+a.z+a.w + c.x+c.y+c.z+c.w;
    #pragma unroll
    for (int off = 16; off; off >>= 1) s += __shfl_down_sync(0xffffffffu, s, off);
    if (lane == 0) {
        float mean = s * (1.0f/256.0f);
        int e = (mean > 0.02f && mean < 0.98f) ? 1 : 0;
        g_edge[token] = e;
        if (e) atomicAdd(&g_raw[b], 1);
    }
}

__global__ void k_fallback() {
    int b = blockIdx.x;
    if (g_raw[b] >= 64) return;
    for (int t = threadIdx.x; t < NTOK; t += blockDim.x) g_edge[b*NTOK + t] = 1;
}

__global__ void k_compact() {
    int b = blockIdx.x, tid = threadIdx.x;
    int t0 = tid * 4;
    int f[4]; int e = 0;
    #pragma unroll
    for (int i = 0; i < 4; i++) { f[i] = g_edge[b*NTOK + t0 + i]; e += f[i]; }
    int lane = tid & 31, wid = tid >> 5;
    int v = e;
    #pragma unroll
    for (int off = 1; off < 32; off <<= 1) {
        int n = __shfl_up_sync(0xffffffffu, v, off);
        if (lane >= off) v += n;
    }
    __shared__ int wsum[32];
    if (lane == 31) wsum[wid] = v;
    __syncthreads();
    if (wid == 0) {
        int wv = wsum[lane];
        #pragma unroll
        for (int off = 1; off < 32; off <<= 1) {
            int n = __shfl_up_sync(0xffffffffu, wv, off);
            if (lane >= off) wv += n;
        }
        wsum[lane] = wv;
    }
    __syncthreads();
    int excl = v - e + (wid ? wsum[wid-1] : 0);
    int eoff = excl, zoff = t0 - excl;
    #pragma unroll
    for (int i = 0; i < 4; i++) {
        if (f[i]) g_eidx[b*NTOK + eoff++] = t0 + i;
        else      g_zidx[b*NTOK + zoff++] = t0 + i;
    }
    if (tid == 1023) { int tot = wsum[31]; g_cntE[b] = tot; g_cntZ[b] = NTOK - tot; }
}

// ---------------- fp16 MMA GEMM (unchanged from R5) ----------------
__device__ __forceinline__ float gelu_exact(float x) {
    return 0.5f * x * (1.0f + erff(x * 0.70710678118654752f));
}

template<int EPI>
__global__ void __launch_bounds__(256)
k_gemm(const float* __restrict__ xfull, const __half* __restrict__ A,
       const __half* __restrict__ W, const float* __restrict__ bias,
       float* __restrict__ dout)
{
    constexpr int K = (EPI == 3) ? HID : DIM;
    constexpr int N = (EPI == 0) ? 3*DIM : (EPI == 2 ? HID : DIM);
    constexpr int NT = K / 32;
    const int* cntp = (EPI >= 2) ? g_cntZ : g_cntE;

    int b = blockIdx.z;
    int M = cntp[b];
    int m0 = blockIdx.y * 128;
    if (m0 >= M) return;
    int n0 = blockIdx.x * 128;
    const __half* Ab = A + (long)b * NTOK * K;

    __shared__ __half As[2][128][40];
    __shared__ __half Bs[2][32][136];

    int tid = threadIdx.x;
    int w = tid >> 5, lane = tid & 31;
    int wm = (w >> 2) * 64, wn = (w & 3) * 32;
    int qr = lane >> 2, qc = lane & 3;

    int  mA[2], cA[2], krB[2], cB[2];
    long arow[2];
    #pragma unroll
    for (int t = 0; t < 2; t++) {
        int task = tid + 256*t;
        mA[t] = task >> 2; cA[t] = (task & 3) * 8;
        int gm = m0 + mA[t];
        arow[t] = (gm < M) ? (long)((EPI == 0) ? g_eidx[b*NTOK + gm] : gm) * K : -1;
        krB[t] = task >> 4; cB[t] = (task & 15) * 8;
    }

    auto issue = [&](int k0, int buf) {
        #pragma unroll
        for (int t = 0; t < 2; t++) {
            const __half* asrc = (arow[t] >= 0) ? (Ab + arow[t] + k0 + cA[t]) : Ab;
            cpa16z(&As[buf][mA[t]][cA[t]], asrc, arow[t] >= 0);
            cpa16(&Bs[buf][krB[t]][cB[t]], W + (long)(k0 + krB[t])*N + n0 + cB[t]);
        }
    };

    float4 acc[4][4];
    #pragma unroll
    for (int i = 0; i < 4; i++)
        #pragma unroll
        for (int j = 0; j < 4; j++) acc[i][j] = make_float4(0,0,0,0);

    issue(0, 0); cpa_commit();
    issue(32, 1); cpa_commit();

    #pragma unroll 1
    for (int it = 0; it < NT; it++) {
        cpa_wait1();
        __syncthreads();
        int buf = it & 1;
        unsigned bfr[4][4];
        #pragma unroll
        for (int ni = 0; ni < 4; ni++)
            ldsm4t(bfr[ni], &Bs[buf][lane][wn + ni*8]);
        #pragma unroll
        for (int ks = 0; ks < 2; ks++) {
            unsigned afr[4][4];
            #pragma unroll
            for (int mi = 0; mi < 4; mi++)
                ldsm4(afr[mi], &As[buf][wm + mi*16 + (lane & 15)][ks*16 + (lane >> 4)*8]);
            #pragma unroll
            for (int ni = 0; ni < 4; ni++)
                #pragma unroll
                for (int mi = 0; mi < 4; mi++)
                    mma16(acc[mi][ni], afr[mi], bfr[ni][ks*2], bfr[ni][ks*2+1]);
        }
        __syncthreads();
        if (it + 2 < NT) issue((it + 2) * 32, buf);
        cpa_commit();
    }

    #pragma unroll
    for (int mi = 0; mi < 4; mi++) {
        int rowA = m0 + wm + mi*16 + qr;
        int rowB = rowA + 8;
        #pragma unroll
        for (int ni = 0; ni < 4; ni++) {
            int col = n0 + wn + ni*8 + qc*2;
            float b0v = bias[col], b1v = bias[col+1];
            float vx = acc[mi][ni].x + b0v, vy = acc[mi][ni].y + b1v;
            float vz = acc[mi][ni].z + b0v, vw = acc[mi][ni].w + b1v;
            if (EPI == 0) {
                int part = col / DIM, cc = col - part*DIM;
                __half* dst = (part == 0) ? g_qh : (part == 1) ? g_kh : g_vh;
                int h = cc >> 6, d = cc & 63;
                long hb = ((long)b*HEADS + h)*NTOK;
                if (rowA < M) *(__half2*)&dst[(hb + rowA)*HD + d] = __floats2half2_rn(vx, vy);
                if (rowB < M) *(__half2*)&dst[(hb + rowB)*HD + d] = __floats2half2_rn(vz, vw);
            } else if (EPI == 1) {
                if (rowA < M) {
                    long o = ((long)b*NTOK + g_eidx[b*NTOK + rowA])*DIM + col;
                    *(float2*)&dout[o] = make_float2(vx + xfull[o], vy + xfull[o+1]);
                }
                if (rowB < M) {
                    long o = ((long)b*NTOK + g_eidx[b*NTOK + rowB])*DIM + col;
                    *(float2*)&dout[o] = make_float2(vz + xfull[o], vw + xfull[o+1]);
                }
            } else if (EPI == 2) {
                if (rowA < M) *(__half2*)&g_h1[((long)b*NTOK + rowA)*HID + col] =
                    __floats2half2_rn(gelu_exact(gelu_exact(vx)), gelu_exact(gelu_exact(vy)));
                if (rowB < M) *(__half2*)&g_h1[((long)b*NTOK + rowB)*HID + col] =
                    __floats2half2_rn(gelu_exact(gelu_exact(vz)), gelu_exact(gelu_exact(vw)));
            } else {
                if (rowA < M) *(float2*)&g_h2[((long)b*NTOK + rowA)*DIM + col] = make_float2(vx, vy);
                if (rowB < M) *(float2*)&g_h2[((long)b*NTOK + rowB)*DIM + col] = make_float2(vz, vw);
            }
        }
    }
}

// ---------------- fp16 flash attention: 8 warps, 128 q/block, 3-stage ring ----------------
#define KT 32
__global__ void __launch_bounds__(256) k_attn() {
    int b = blockIdx.z, h = blockIdx.y;
    int M = g_cntE[b];
    int m0 = blockIdx.x * 128;
    if (m0 >= M) return;
    int tid = threadIdx.x, w = tid >> 5, lane = tid & 31;
    int qr = lane >> 2, qc = lane & 3;
    long base = ((long)b*HEADS + h)*NTOK*HD;

    __shared__ __half Ks[3][KT][72];
    __shared__ __half Vs[3][KT][72];

    int r0 = m0 + w*16 + qr, r1 = r0 + 8;
    bool v0 = r0 < M, v1 = r1 < M;
    const __half* q0p = g_qh + base + (long)r0*HD;
    const __half* q1p = g_qh + base + (long)r1*HD;
    unsigned qf[4][4];
    #pragma unroll
    for (int ks = 0; ks < 4; ks++) {
        int c = ks*16 + qc*2;
        qf[ks][0] = v0 ? *(const unsigned*)&q0p[c]   : 0u;
        qf[ks][1] = v1 ? *(const unsigned*)&q1p[c]   : 0u;
        qf[ks][2] = v0 ? *(const unsigned*)&q0p[c+8] : 0u;
        qf[ks][3] = v1 ? *(const unsigned*)&q1p[c+8] : 0u;
    }

    // loader: K 256 chunks + V 256 chunks; 2 tasks/thread (256 threads)
    auto issue = [&](int kb, int buf) {
        #pragma unroll
        for (int t = 0; t < 2; t++) {
            int task = tid + 256*t;            // 0..511
            int mat  = task >> 8;              // 0 = K, 1 = V
            int t2   = task & 255;
            int row  = t2 >> 3;
            int c8   = (t2 & 7) * 8;
            bool ok = (kb + row) < M;
            const __half* src = (mat ? g_vh : g_kh) + base + (long)(kb + (ok ? row : 0))*HD + c8;
            if (mat) cpa16z(&Vs[buf][row][c8], src, ok);
            else     cpa16z(&Ks[buf][row][c8], src, ok);
        }
    };

    float4 oacc[8];
    #pragma unroll
    for (int i = 0; i < 8; i++) oacc[i] = make_float4(0,0,0,0);
    float mx0 = -1e30f, mx1 = -1e30f, l0 = 0.0f, l1 = 0.0f;
    const float SC = 0.125f * 1.44269504088896340736f;  // 1/sqrt(64) * log2(e)

    int ntiles = (M + KT - 1) / KT;
    issue(0, 0); cpa_commit();
    if (ntiles > 1) issue(KT, 1);
    cpa_commit();

    int buf = 0;
    #pragma unroll 1
    for (int kt = 0; kt < ntiles; kt++) {
        int kb = kt * KT;
        cpa_wait1();
        __syncthreads();

        // S = Q K^T
        float4 s[4];
        #pragma unroll
        for (int nt = 0; nt < 4; nt++) s[nt] = make_float4(0,0,0,0);
        #pragma unroll
        for (int dh = 0; dh < 2; dh++) {
            unsigned kf[4][4];
            #pragma unroll
            for (int nt = 0; nt < 4; nt++)
                ldsm4(kf[nt], &Ks[buf][nt*8 + (lane & 7)][(lane >> 3)*8 + dh*32]);
            #pragma unroll
            for (int ksd = 0; ksd < 2; ksd++)
                #pragma unroll
                for (int nt = 0; nt < 4; nt++)
                    mma16(s[nt], qf[dh*2 + ksd], kf[nt][ksd*2], kf[nt][ksd*2+1]);
        }
        // scale (log2 domain), mask, row max
        float t0 = -1e30f, t1 = -1e30f;
        #pragma unroll
        for (int nt = 0; nt < 4; nt++) {
            s[nt].x *= SC; s[nt].y *= SC; s[nt].z *= SC; s[nt].w *= SC;
            int c0 = kb + nt*8 + qc*2;
            if (c0     >= M) { s[nt].x = -1e30f; s[nt].z = -1e30f; }
            if (c0 + 1 >= M) { s[nt].y = -1e30f; s[nt].w = -1e30f; }
            t0 = fmaxf(t0, fmaxf(s[nt].x, s[nt].y));
            t1 = fmaxf(t1, fmaxf(s[nt].z, s[nt].w));
        }
        t0 = fmaxf(t0, __shfl_xor_sync(0xffffffffu, t0, 1));
        t0 = fmaxf(t0, __shfl_xor_sync(0xffffffffu, t0, 2));
        t1 = fmaxf(t1, __shfl_xor_sync(0xffffffffu, t1, 1));
        t1 = fmaxf(t1, __shfl_xor_sync(0xffffffffu, t1, 2));
        float nm0 = fmaxf(mx0, t0), nm1 = fmaxf(mx1, t1);
        float cr0 = ex2(mx0 - nm0), cr1 = ex2(mx1 - nm1);
        l0 *= cr0; l1 *= cr1;
        #pragma unroll
        for (int i = 0; i < 8; i++) {
            oacc[i].x *= cr0; oacc[i].y *= cr0;
            oacc[i].z *= cr1; oacc[i].w *= cr1;
        }
        mx0 = nm0; mx1 = nm1;

        // exp2 -> fp16 A-frags for PV
        float ps0 = 0.0f, ps1 = 0.0f;
        unsigned pa[2][4];
        #pragma unroll
        for (int nt = 0; nt < 4; nt++) {
            float px = ex2(s[nt].x - mx0), py = ex2(s[nt].y - mx0);
            float pz = ex2(s[nt].z - mx1), pw = ex2(s[nt].w - mx1);
            ps0 += px + py; ps1 += pz + pw;
            int ks = nt >> 1, hi = (nt & 1) * 2;
            pa[ks][hi]     = h2u(__floats2half2_rn(px, py));
            pa[ks][hi + 1] = h2u(__floats2half2_rn(pz, pw));
        }
        ps0 += __shfl_xor_sync(0xffffffffu, ps0, 1);
        ps0 += __shfl_xor_sync(0xffffffffu, ps0, 2);
        ps1 += __shfl_xor_sync(0xffffffffu, ps1, 1);
        ps1 += __shfl_xor_sync(0xffffffffu, ps1, 2);
        l0 += ps0; l1 += ps1;

        // O += P V
        #pragma unroll
        for (int ks = 0; ks < 2; ks++) {
            unsigned vf[4][4];
            #pragma unroll
            for (int dp = 0; dp < 4; dp++)
                ldsm4t(vf[dp], &Vs[buf][16*ks + ((lane >> 3) & 1)*8 + (lane & 7)]
                                  [dp*16 + (lane >> 4)*8]);
            #pragma unroll
            for (int nt = 0; nt < 8; nt++)
                mma16(oacc[nt], pa[ks], vf[nt >> 1][(nt & 1)*2], vf[nt >> 1][(nt & 1)*2 + 1]);
        }

        // prefetch tile kt+2 into the buffer consumed at iteration kt-1
        if (kt + 2 < ntiles) {
            int nb = buf + 2; if (nb >= 3) nb -= 3;
            issue(kb + 2*KT, nb);
        }
        cpa_commit();
        if (++buf == 3) buf = 0;
    }

    float inv0 = 1.0f / l0, inv1 = 1.0f / l1;
    #pragma unroll
    for (int nt = 0; nt < 8; nt++) {
        int col = h*64 + nt*8 + qc*2;
        if (v0) *(__half2*)&g_oh[((long)b*NTOK + r0)*DIM + col] =
            __floats2half2_rn(oacc[nt].x * inv0, oacc[nt].y * inv0);
        if (v1) *(__half2*)&g_oh[((long)b*NTOK + r1)*DIM + col] =
            __floats2half2_rn(oacc[nt].z * inv1, oacc[nt].w * inv1);
    }
}

// ---------------- LayerNorm on easy rows (fp16 out) ----------------
__global__ void k_ln(const float* __restrict__ x, const float* __restrict__ g,
                     const float* __restrict__ be) {
    int b = blockIdx.y, m = blockIdx.x;
    if (m >= g_cntZ[b]) return;
    int tok = g_zidx[b*NTOK + m];
    const float* row = x + ((long)b*NTOK + tok)*DIM;
    int tid = threadIdx.x;
    float v[3];
    float s = 0.0f, s2 = 0.0f;
    #pragma unroll
    for (int i = 0; i < 3; i++) {
        v[i] = row[tid + i*256];
        s += v[i]; s2 += v[i]*v[i];
    }
    __shared__ float r0[256], r1[256];
    r0[tid] = s; r1[tid] = s2;
    __syncthreads();
    for (int off = 128; off; off >>= 1) {
        if (tid < off) { r0[tid] += r0[tid+off]; r1[tid] += r1[tid+off]; }
        __syncthreads();
    }
    float mu  = r0[0] * (1.0f/DIM);
    float var = r1[0] * (1.0f/DIM) - mu*mu;
    float rs  = rsqrtf(var + 1e-5f);
    __half* outp = g_hln + ((long)b*NTOK + m)*DIM;
    #pragma unroll
    for (int i = 0; i < 3; i++) {
        int c = tid + i*256;
        outp[c] = __float2half_rn((v[i] - mu) * rs * g[c] + be[c]);
    }
}

// ---------------- 2-stage masked mean pool + fused ECA ----------------
__global__ void k_pool1() {
    int b = blockIdx.z, part = blockIdx.y;
    int c = blockIdx.x * 256 + threadIdx.x;
    int cz = g_cntZ[b];
    int chunk = (cz + 15) / 16;
    int mlo = part * chunk, mhi = min(mlo + chunk, cz);
    float s = 0.0f;
    for (int m = mlo; m < mhi; m++) s += g_h2[((long)b*NTOK + m)*DIM + c];
    g_poolp[(b*16 + part)*DIM + c] = s;
}

__global__ void k_pool2(const float* __restrict__ w) {
    int b = blockIdx.x, c = threadIdx.x;
    __shared__ float pooled[DIM];
    float s = 0.0f;
    #pragma unroll
    for (int p = 0; p < 16; p++) s += g_poolp[(b*16 + p)*DIM + c];
    pooled[c] = s / fmaxf((float)g_cntZ[b], 1.0f);
    __syncthreads();
    float g = 0.0f;
    #pragma unroll
    for (int tt = 0; tt < 5; tt++) {
        int cc = c + tt - 2;
        if (cc >= 0 && cc < DIM) g += w[tt] * pooled[cc];
    }
    g_sig[b*DIM + c] = 1.0f / (1.0f + __expf(-g));
}

// ---------------- LTRM scatter ----------------
__global__ void k_ltrm(const float* __restrict__ x, float* __restrict__ out) {
    int b = blockIdx.y, m = blockIdx.x;
    if (m >= g_cntZ[b]) return;
    int tok = g_zidx[b*NTOK + m];
    long ro = ((long)b*NTOK + tok)*DIM;
    long ri = ((long)b*NTOK + m)*DIM;
    for (int c = threadIdx.x; c < DIM; c += 256)
        out[ro + c] = x[ro + c] + g_h2[ri + c] * g_sig[b*DIM + c];
}

// ---------------- launch: fork-join two streams inside capture ----------------
extern "C" void kernel_launch(void* const* d_in, const int* in_sizes, int n_in,
                              void* d_out, int out_size) {
    const float* x      = (const float*)d_in[0];
    const float* hint   = (const float*)d_in[1];
    const float* qkv_w  = (const float*)d_in[2];
    const float* qkv_b  = (const float*)d_in[3];
    const float* proj_w = (const float*)d_in[4];
    const float* proj_b = (const float*)d_in[5];
    const float* ln_g   = (const float*)d_in[6];
    const float* ln_b   = (const float*)d_in[7];
    const float* fc1_w  = (const float*)d_in[8];
    const float* fc1_b  = (const float*)d_in[9];
    const float* fc2_w  = (const float*)d_in[10];
    const float* fc2_b  = (const float*)d_in[11];
    const float* eca_w  = (const float*)d_in[12];
    float* out = (float*)d_out;

    __half *d_xh, *d_wqkv, *d_wproj, *d_wfc1, *d_wfc2, *d_oh, *d_hln, *d_h1;
    cudaGetSymbolAddress((void**)&d_xh,   g_xh);
    cudaGetSymbolAddress((void**)&d_wqkv, g_wqkv);
    cudaGetSymbolAddress((void**)&d_wproj,g_wproj);
    cudaGetSymbolAddress((void**)&d_wfc1, g_wfc1);
    cudaGetSymbolAddress((void**)&d_wfc2, g_wfc2);
    cudaGetSymbolAddress((void**)&d_oh,  g_oh);
    cudaGetSymbolAddress((void**)&d_hln, g_hln);
    cudaGetSymbolAddress((void**)&d_h1,  g_h1);

    cudaStream_t s2;
    cudaStreamCreateWithFlags(&s2, cudaStreamNonBlocking);
    cudaEvent_t e0, eCvt, eCompact, eEasy;
    cudaEventCreateWithFlags(&e0,       cudaEventDisableTiming);
    cudaEventCreateWithFlags(&eCvt,     cudaEventDisableTiming);
    cudaEventCreateWithFlags(&eCompact, cudaEventDisableTiming);
    cudaEventCreateWithFlags(&eEasy,    cudaEventDisableTiming);

    // prologue on main stream; fork conversions onto s2
    k_reset<<<1, 32>>>();
    cudaEventRecord(e0, 0);
    cudaStreamWaitEvent(s2, e0, 0);

    k_cvt<<<BB*NTOK*DIM/2048, 256, 0, s2>>>(x,      d_xh,   BB*NTOK*DIM);
    k_cvt<<<DIM*3*DIM/2048,  256, 0, s2>>>(qkv_w,  d_wqkv, DIM*3*DIM);
    k_cvt<<<DIM*DIM/2048,    256, 0, s2>>>(proj_w, d_wproj,DIM*DIM);
    k_cvt<<<DIM*HID/2048,    256, 0, s2>>>(fc1_w,  d_wfc1, DIM*HID);
    k_cvt<<<HID*DIM/2048,    256, 0, s2>>>(fc2_w,  d_wfc2, HID*DIM);
    cudaEventRecord(eCvt, s2);

    k_edge    <<<BB*NTOK/8, 256>>>(hint);
    k_fallback<<<BB, 256>>>();
    k_compact <<<BB, 1024>>>();
    cudaEventRecord(eCompact, 0);

    // edge path on main stream (needs conversions)
    cudaStreamWaitEvent(0, eCvt, 0);
    k_gemm<0><<<dim3(3*DIM/128, NTOK/128, BB), 256>>>(x, d_xh, d_wqkv, qkv_b, out);
    k_attn   <<<dim3(NTOK/128, HEADS, BB), 256>>>();
    k_gemm<1><<<dim3(DIM/128, NTOK/128, BB), 256>>>(x, d_oh, d_wproj, proj_b, out);

    // easy path on s2 (needs compact)
    cudaStreamWaitEvent(s2, eCompact, 0);
    k_ln     <<<dim3(NTOK, BB), 256, 0, s2>>>(x, ln_g, ln_b);
    k_gemm<2><<<dim3(HID/128, NTOK/128, BB), 256, 0, s2>>>(x, d_hln, d_wfc1, fc1_b, out);
    k_gemm<3><<<dim3(DIM/128, NTOK/128, BB), 256, 0, s2>>>(x, d_h1, d_wfc2, fc2_b, out);
    k_pool1  <<<dim3(DIM/256, 16, BB), 256, 0, s2>>>();
    k_pool2  <<<BB, DIM, 0, s2>>>(eca_w);
    k_ltrm   <<<dim3(NTOK, BB), 256, 0, s2>>>(x, out);
    cudaEventRecord(eEasy, s2);

    // join
    cudaStreamWaitEvent(0, eEasy, 0);

    cudaEventDestroy(e0);
    cudaEventDestroy(eCvt);
    cudaEventDestroy(eCompact);
    cudaEventDestroy(eEasy);
    cudaStreamDestroy(s2);
}

// round 9
// speedup vs baseline: 7.7132x; 1.0824x over previous
#include <cuda_runtime.h>
#include <cuda_fp16.h>
#include <math.h>
#include <cstdint>

#define BB     2
#define NTOK   4096
#define DIM    768
#define HEADS  12
#define HD     64
#define HID    1536
#define HINTR  1024

// ---------------- device scratch ----------------
__device__ int    g_edge[BB*NTOK];
__device__ int    g_cntE[BB];
__device__ int    g_cntZ[BB];
__device__ int    g_eidx[BB*NTOK];
__device__ int    g_zidx[BB*NTOK];
__device__ __half g_xh [(size_t)BB*NTOK*DIM];
__device__ __half g_wqkv[(size_t)DIM*3*DIM];
__device__ __half g_wproj[(size_t)DIM*DIM];
__device__ __half g_wfc1[(size_t)DIM*HID];
__device__ __half g_wfc2[(size_t)HID*DIM];
__device__ __half g_qh [(size_t)BB*HEADS*NTOK*HD];
__device__ __half g_kh [(size_t)BB*HEADS*NTOK*HD];
__device__ __half g_vh [(size_t)BB*HEADS*NTOK*HD];
__device__ __half g_oh [(size_t)BB*NTOK*DIM];
__device__ __half g_hln[(size_t)BB*NTOK*DIM];
__device__ __half g_h1 [(size_t)BB*NTOK*HID];
__device__ float  g_h2 [(size_t)BB*NTOK*DIM];
__device__ float  g_poolp[BB*16*DIM];
__device__ float  g_sig [BB*DIM];

// ---------------- asm helpers ----------------
__device__ __forceinline__ void mma16(float4& d, const unsigned* a, unsigned b0, unsigned b1) {
    asm volatile(
        "mma.sync.aligned.m16n8k16.row.col.f32.f16.f16.f32 "
        "{%0,%1,%2,%3}, {%4,%5,%6,%7}, {%8,%9}, {%0,%1,%2,%3};\n"
        : "+f"(d.x), "+f"(d.y), "+f"(d.z), "+f"(d.w)
        : "r"(a[0]), "r"(a[1]), "r"(a[2]), "r"(a[3]), "r"(b0), "r"(b1));
}
__device__ __forceinline__ void ldsm4(unsigned* r, const void* p) {
    unsigned a = (unsigned)__cvta_generic_to_shared(p);
    asm volatile("ldmatrix.sync.aligned.m8n8.x4.shared.b16 {%0,%1,%2,%3}, [%4];\n"
        : "=r"(r[0]), "=r"(r[1]), "=r"(r[2]), "=r"(r[3]) : "r"(a));
}
__device__ __forceinline__ void ldsm4t(unsigned* r, const void* p) {
    unsigned a = (unsigned)__cvta_generic_to_shared(p);
    asm volatile("ldmatrix.sync.aligned.m8n8.x4.trans.shared.b16 {%0,%1,%2,%3}, [%4];\n"
        : "=r"(r[0]), "=r"(r[1]), "=r"(r[2]), "=r"(r[3]) : "r"(a));
}
__device__ __forceinline__ void cpa16(void* smem, const void* gmem) {
    unsigned s = (unsigned)__cvta_generic_to_shared(smem);
    asm volatile("cp.async.cg.shared.global [%0], [%1], 16;\n" :: "r"(s), "l"(gmem));
}
__device__ __forceinline__ void cpa16z(void* smem, const void* gmem, bool pred) {
    unsigned s = (unsigned)__cvta_generic_to_shared(smem);
    int sz = pred ? 16 : 0;
    asm volatile("cp.async.cg.shared.global [%0], [%1], 16, %2;\n" :: "r"(s), "l"(gmem), "r"(sz));
}
__device__ __forceinline__ void cpa_commit() { asm volatile("cp.async.commit_group;\n"); }
__device__ __forceinline__ void cpa_wait1()  { asm volatile("cp.async.wait_group 1;\n"); }
__device__ __forceinline__ unsigned h2u(__half2 h) { return *(unsigned*)&h; }
__device__ __forceinline__ float ex2(float x) {
    float y; asm("ex2.approx.ftz.f32 %0, %1;" : "=f"(y) : "f"(x)); return y;
}

// ---------------- merged fp32 -> fp16 conversion for all tensors ----------------
// segments (2048 elems/block): x 3072 | qkv 864 | proj 288 | fc1 576 | fc2 576
__global__ void k_cvtall(const float* __restrict__ x,  const float* __restrict__ w0,
                         const float* __restrict__ w1, const float* __restrict__ w2,
                         const float* __restrict__ w3) {
    int bx = blockIdx.x;
    const float* src; __half* dst; long base;
    if (bx < 3072)      { src = x;  dst = g_xh;    base = (long)bx * 2048; }
    else if (bx < 3936) { src = w0; dst = g_wqkv;  base = (long)(bx - 3072) * 2048; }
    else if (bx < 4224) { src = w1; dst = g_wproj; base = (long)(bx - 3936) * 2048; }
    else if (bx < 4800) { src = w2; dst = g_wfc1;  base = (long)(bx - 4224) * 2048; }
    else                { src = w3; dst = g_wfc2;  base = (long)(bx - 4800) * 2048; }
    long i = base + threadIdx.x * 8;
    float4 f0 = *(const float4*)(src + i);
    float4 f1 = *(const float4*)(src + i + 4);
    __half2 h[4] = { __floats2half2_rn(f0.x, f0.y), __floats2half2_rn(f0.z, f0.w),
                     __floats2half2_rn(f1.x, f1.y), __floats2half2_rn(f1.z, f1.w) };
    *(uint4*)(dst + i) = *(uint4*)h;
}

// ---------------- edge mask ----------------
__global__ void k_edge(const float* __restrict__ hint) {
    int warp = threadIdx.x >> 5, lane = threadIdx.x & 31;
    int token = blockIdx.x * 8 + warp;
    int b = token / NTOK, t = token % NTOK;
    int ty = t >> 6, tx = t & 63;
    const float* base = hint + (size_t)b*HINTR*HINTR + (size_t)(ty*16)*HINTR + tx*16;
    int r = lane >> 1, half = lane & 1;
    const float4* p = (const float4*)(base + (size_t)r*HINTR + half*8);
    float4 a = p[0], c = p[1];
    float s = a.x+a.y+a.z+a.w + c.x+c.y+c.z+c.w;
    #pragma unroll
    for (int off = 16; off; off >>= 1) s += __shfl_down_sync(0xffffffffu, s, off);
    if (lane == 0) {
        float mean = s * (1.0f/256.0f);
        g_edge[token] = (mean > 0.02f && mean < 0.98f) ? 1 : 0;
    }
}

// ---------------- compaction with folded fallback ----------------
__global__ void k_compact() {
    int b = blockIdx.x, tid = threadIdx.x;
    int t0 = tid * 4;
    int f[4]; int e = 0;
    #pragma unroll
    for (int i = 0; i < 4; i++) { f[i] = g_edge[b*NTOK + t0 + i]; e += f[i]; }
    int lane = tid & 31, wid = tid >> 5;
    int v = e;
    #pragma unroll
    for (int off = 1; off < 32; off <<= 1) {
        int n = __shfl_up_sync(0xffffffffu, v, off);
        if (lane >= off) v += n;
    }
    __shared__ int wsum[32];
    if (lane == 31) wsum[wid] = v;
    __syncthreads();
    if (wid == 0) {
        int wv = wsum[lane];
        #pragma unroll
        for (int off = 1; off < 32; off <<= 1) {
            int n = __shfl_up_sync(0xffffffffu, wv, off);
            if (lane >= off) wv += n;
        }
        wsum[lane] = wv;
    }
    __syncthreads();
    int tot = wsum[31];
    if (tot < 64) {     // fallback: route everything to attention
        #pragma unroll
        for (int i = 0; i < 4; i++) g_eidx[b*NTOK + t0 + i] = t0 + i;
        if (tid == 1023) { g_cntE[b] = NTOK; g_cntZ[b] = 0; }
        return;
    }
    int excl = v - e + (wid ? wsum[wid-1] : 0);
    int eoff = excl, zoff = t0 - excl;
    #pragma unroll
    for (int i = 0; i < 4; i++) {
        if (f[i]) g_eidx[b*NTOK + eoff++] = t0 + i;
        else      g_zidx[b*NTOK + zoff++] = t0 + i;
    }
    if (tid == 1023) { g_cntE[b] = tot; g_cntZ[b] = NTOK - tot; }
}

// ---------------- fp16 MMA GEMM (R6-proven) ----------------
__device__ __forceinline__ float gelu_exact(float x) {
    return 0.5f * x * (1.0f + erff(x * 0.70710678118654752f));
}

template<int EPI>
__global__ void __launch_bounds__(256)
k_gemm(const float* __restrict__ xfull, const __half* __restrict__ A,
       const __half* __restrict__ W, const float* __restrict__ bias,
       float* __restrict__ dout)
{
    constexpr int K = (EPI == 3) ? HID : DIM;
    constexpr int N = (EPI == 0) ? 3*DIM : (EPI == 2 ? HID : DIM);
    constexpr int NT = K / 32;
    const int* cntp = (EPI >= 2) ? g_cntZ : g_cntE;

    int b = blockIdx.z;
    int M = cntp[b];
    int m0 = blockIdx.y * 128;
    if (m0 >= M) return;
    int n0 = blockIdx.x * 128;
    const __half* Ab = A + (long)b * NTOK * K;

    __shared__ __half As[2][128][40];
    __shared__ __half Bs[2][32][136];

    int tid = threadIdx.x;
    int w = tid >> 5, lane = tid & 31;
    int wm = (w >> 2) * 64, wn = (w & 3) * 32;
    int qr = lane >> 2, qc = lane & 3;

    int  mA[2], cA[2], krB[2], cB[2];
    long arow[2];
    #pragma unroll
    for (int t = 0; t < 2; t++) {
        int task = tid + 256*t;
        mA[t] = task >> 2; cA[t] = (task & 3) * 8;
        int gm = m0 + mA[t];
        arow[t] = (gm < M) ? (long)((EPI == 0) ? g_eidx[b*NTOK + gm] : gm) * K : -1;
        krB[t] = task >> 4; cB[t] = (task & 15) * 8;
    }

    auto issue = [&](int k0, int buf) {
        #pragma unroll
        for (int t = 0; t < 2; t++) {
            const __half* asrc = (arow[t] >= 0) ? (Ab + arow[t] + k0 + cA[t]) : Ab;
            cpa16z(&As[buf][mA[t]][cA[t]], asrc, arow[t] >= 0);
            cpa16(&Bs[buf][krB[t]][cB[t]], W + (long)(k0 + krB[t])*N + n0 + cB[t]);
        }
    };

    float4 acc[4][4];
    #pragma unroll
    for (int i = 0; i < 4; i++)
        #pragma unroll
        for (int j = 0; j < 4; j++) acc[i][j] = make_float4(0,0,0,0);

    issue(0, 0); cpa_commit();
    issue(32, 1); cpa_commit();

    #pragma unroll 1
    for (int it = 0; it < NT; it++) {
        cpa_wait1();
        __syncthreads();
        int buf = it & 1;
        unsigned bfr[4][4];
        #pragma unroll
        for (int ni = 0; ni < 4; ni++)
            ldsm4t(bfr[ni], &Bs[buf][lane][wn + ni*8]);
        #pragma unroll
        for (int ks = 0; ks < 2; ks++) {
            unsigned afr[4][4];
            #pragma unroll
            for (int mi = 0; mi < 4; mi++)
                ldsm4(afr[mi], &As[buf][wm + mi*16 + (lane & 15)][ks*16 + (lane >> 4)*8]);
            #pragma unroll
            for (int ni = 0; ni < 4; ni++)
                #pragma unroll
                for (int mi = 0; mi < 4; mi++)
                    mma16(acc[mi][ni], afr[mi], bfr[ni][ks*2], bfr[ni][ks*2+1]);
        }
        __syncthreads();
        if (it + 2 < NT) issue((it + 2) * 32, buf);
        cpa_commit();
    }

    #pragma unroll
    for (int mi = 0; mi < 4; mi++) {
        int rowA = m0 + wm + mi*16 + qr;
        int rowB = rowA + 8;
        #pragma unroll
        for (int ni = 0; ni < 4; ni++) {
            int col = n0 + wn + ni*8 + qc*2;
            float b0v = bias[col], b1v = bias[col+1];
            float vx = acc[mi][ni].x + b0v, vy = acc[mi][ni].y + b1v;
            float vz = acc[mi][ni].z + b0v, vw = acc[mi][ni].w + b1v;
            if (EPI == 0) {
                int part = col / DIM, cc = col - part*DIM;
                __half* dst = (part == 0) ? g_qh : (part == 1) ? g_kh : g_vh;
                int h = cc >> 6, d = cc & 63;
                long hb = ((long)b*HEADS + h)*NTOK;
                if (rowA < M) *(__half2*)&dst[(hb + rowA)*HD + d] = __floats2half2_rn(vx, vy);
                if (rowB < M) *(__half2*)&dst[(hb + rowB)*HD + d] = __floats2half2_rn(vz, vw);
            } else if (EPI == 1) {
                if (rowA < M) {
                    long o = ((long)b*NTOK + g_eidx[b*NTOK + rowA])*DIM + col;
                    *(float2*)&dout[o] = make_float2(vx + xfull[o], vy + xfull[o+1]);
                }
                if (rowB < M) {
                    long o = ((long)b*NTOK + g_eidx[b*NTOK + rowB])*DIM + col;
                    *(float2*)&dout[o] = make_float2(vz + xfull[o], vw + xfull[o+1]);
                }
            } else if (EPI == 2) {
                if (rowA < M) *(__half2*)&g_h1[((long)b*NTOK + rowA)*HID + col] =
                    __floats2half2_rn(gelu_exact(gelu_exact(vx)), gelu_exact(gelu_exact(vy)));
                if (rowB < M) *(__half2*)&g_h1[((long)b*NTOK + rowB)*HID + col] =
                    __floats2half2_rn(gelu_exact(gelu_exact(vz)), gelu_exact(gelu_exact(vw)));
            } else {
                if (rowA < M) *(float2*)&g_h2[((long)b*NTOK + rowA)*DIM + col] = make_float2(vx, vy);
                if (rowB < M) *(float2*)&g_h2[((long)b*NTOK + rowB)*DIM + col] = make_float2(vz, vw);
            }
        }
    }
}

// ---------------- fp16 flash attention: 8 warps, 128 q/block, 3-stage ring ----------------
#define KT 32
__global__ void __launch_bounds__(256) k_attn() {
    int b = blockIdx.z, h = blockIdx.y;
    int M = g_cntE[b];
    int m0 = blockIdx.x * 128;
    if (m0 >= M) return;
    int tid = threadIdx.x, w = tid >> 5, lane = tid & 31;
    int qr = lane >> 2, qc = lane & 3;
    long base = ((long)b*HEADS + h)*NTOK*HD;

    __shared__ __half Ks[3][KT][72];
    __shared__ __half Vs[3][KT][72];

    int r0 = m0 + w*16 + qr, r1 = r0 + 8;
    bool v0 = r0 < M, v1 = r1 < M;
    const __half* q0p = g_qh + base + (long)r0*HD;
    const __half* q1p = g_qh + base + (long)r1*HD;
    unsigned qf[4][4];
    #pragma unroll
    for (int ks = 0; ks < 4; ks++) {
        int c = ks*16 + qc*2;
        qf[ks][0] = v0 ? *(const unsigned*)&q0p[c]   : 0u;
        qf[ks][1] = v1 ? *(const unsigned*)&q1p[c]   : 0u;
        qf[ks][2] = v0 ? *(const unsigned*)&q0p[c+8] : 0u;
        qf[ks][3] = v1 ? *(const unsigned*)&q1p[c+8] : 0u;
    }

    auto issue = [&](int kb, int buf) {
        #pragma unroll
        for (int t = 0; t < 2; t++) {
            int task = tid + 256*t;
            int mat  = task >> 8;
            int t2   = task & 255;
            int row  = t2 >> 3;
            int c8   = (t2 & 7) * 8;
            bool ok = (kb + row) < M;
            const __half* src = (mat ? g_vh : g_kh) + base + (long)(kb + (ok ? row : 0))*HD + c8;
            if (mat) cpa16z(&Vs[buf][row][c8], src, ok);
            else     cpa16z(&Ks[buf][row][c8], src, ok);
        }
    };

    float4 oacc[8];
    #pragma unroll
    for (int i = 0; i < 8; i++) oacc[i] = make_float4(0,0,0,0);
    float mx0 = -1e30f, mx1 = -1e30f, l0 = 0.0f, l1 = 0.0f;
    const float SC = 0.125f * 1.44269504088896340736f;

    int ntiles = (M + KT - 1) / KT;
    issue(0, 0); cpa_commit();
    if (ntiles > 1) issue(KT, 1);
    cpa_commit();

    int buf = 0;
    #pragma unroll 1
    for (int kt = 0; kt < ntiles; kt++) {
        int kb = kt * KT;
        cpa_wait1();
        __syncthreads();

        float4 s[4];
        #pragma unroll
        for (int nt = 0; nt < 4; nt++) s[nt] = make_float4(0,0,0,0);
        #pragma unroll
        for (int dh = 0; dh < 2; dh++) {
            unsigned kf[4][4];
            #pragma unroll
            for (int nt = 0; nt < 4; nt++)
                ldsm4(kf[nt], &Ks[buf][nt*8 + (lane & 7)][(lane >> 3)*8 + dh*32]);
            #pragma unroll
            for (int ksd = 0; ksd < 2; ksd++)
                #pragma unroll
                for (int nt = 0; nt < 4; nt++)
                    mma16(s[nt], qf[dh*2 + ksd], kf[nt][ksd*2], kf[nt][ksd*2+1]);
        }
        float t0 = -1e30f, t1 = -1e30f;
        #pragma unroll
        for (int nt = 0; nt < 4; nt++) {
            s[nt].x *= SC; s[nt].y *= SC; s[nt].z *= SC; s[nt].w *= SC;
            int c0 = kb + nt*8 + qc*2;
            if (c0     >= M) { s[nt].x = -1e30f; s[nt].z = -1e30f; }
            if (c0 + 1 >= M) { s[nt].y = -1e30f; s[nt].w = -1e30f; }
            t0 = fmaxf(t0, fmaxf(s[nt].x, s[nt].y));
            t1 = fmaxf(t1, fmaxf(s[nt].z, s[nt].w));
        }
        t0 = fmaxf(t0, __shfl_xor_sync(0xffffffffu, t0, 1));
        t0 = fmaxf(t0, __shfl_xor_sync(0xffffffffu, t0, 2));
        t1 = fmaxf(t1, __shfl_xor_sync(0xffffffffu, t1, 1));
        t1 = fmaxf(t1, __shfl_xor_sync(0xffffffffu, t1, 2));
        float nm0 = fmaxf(mx0, t0), nm1 = fmaxf(mx1, t1);
        bool nochg = (nm0 == mx0) && (nm1 == mx1);
        if (!__all_sync(0xffffffffu, nochg)) {
            float cr0 = ex2(mx0 - nm0), cr1 = ex2(mx1 - nm1);
            l0 *= cr0; l1 *= cr1;
            #pragma unroll
            for (int i = 0; i < 8; i++) {
                oacc[i].x *= cr0; oacc[i].y *= cr0;
                oacc[i].z *= cr1; oacc[i].w *= cr1;
            }
        }
        mx0 = nm0; mx1 = nm1;

        float ps0 = 0.0f, ps1 = 0.0f;
        unsigned pa[2][4];
        #pragma unroll
        for (int nt = 0; nt < 4; nt++) {
            float px = ex2(s[nt].x - mx0), py = ex2(s[nt].y - mx0);
            float pz = ex2(s[nt].z - mx1), pw = ex2(s[nt].w - mx1);
            ps0 += px + py; ps1 += pz + pw;
            int ks = nt >> 1, hi = (nt & 1) * 2;
            pa[ks][hi]     = h2u(__floats2half2_rn(px, py));
            pa[ks][hi + 1] = h2u(__floats2half2_rn(pz, pw));
        }
        ps0 += __shfl_xor_sync(0xffffffffu, ps0, 1);
        ps0 += __shfl_xor_sync(0xffffffffu, ps0, 2);
        ps1 += __shfl_xor_sync(0xffffffffu, ps1, 1);
        ps1 += __shfl_xor_sync(0xffffffffu, ps1, 2);
        l0 += ps0; l1 += ps1;

        #pragma unroll
        for (int ks = 0; ks < 2; ks++) {
            unsigned vf[4][4];
            #pragma unroll
            for (int dp = 0; dp < 4; dp++)
                ldsm4t(vf[dp], &Vs[buf][16*ks + ((lane >> 3) & 1)*8 + (lane & 7)]
                                  [dp*16 + (lane >> 4)*8]);
            #pragma unroll
            for (int nt = 0; nt < 8; nt++)
                mma16(oacc[nt], pa[ks], vf[nt >> 1][(nt & 1)*2], vf[nt >> 1][(nt & 1)*2 + 1]);
        }

        if (kt + 2 < ntiles) {
            int nb = buf + 2; if (nb >= 3) nb -= 3;
            issue(kb + 2*KT, nb);
        }
        cpa_commit();
        if (++buf == 3) buf = 0;
    }

    float inv0 = 1.0f / l0, inv1 = 1.0f / l1;
    #pragma unroll
    for (int nt = 0; nt < 8; nt++) {
        int col = h*64 + nt*8 + qc*2;
        if (v0) *(__half2*)&g_oh[((long)b*NTOK + r0)*DIM + col] =
            __floats2half2_rn(oacc[nt].x * inv0, oacc[nt].y * inv0);
        if (v1) *(__half2*)&g_oh[((long)b*NTOK + r1)*DIM + col] =
            __floats2half2_rn(oacc[nt].z * inv1, oacc[nt].w * inv1);
    }
}

// ---------------- LayerNorm on easy rows (fp16 out) ----------------
__global__ void k_ln(const float* __restrict__ x, const float* __restrict__ g,
                     const float* __restrict__ be) {
    int b = blockIdx.y, m = blockIdx.x;
    if (m >= g_cntZ[b]) return;
    int tok = g_zidx[b*NTOK + m];
    const float* row = x + ((long)b*NTOK + tok)*DIM;
    int tid = threadIdx.x;
    float v[3];
    float s = 0.0f, s2 = 0.0f;
    #pragma unroll
    for (int i = 0; i < 3; i++) {
        v[i] = row[tid + i*256];
        s += v[i]; s2 += v[i]*v[i];
    }
    __shared__ float r0[256], r1[256];
    r0[tid] = s; r1[tid] = s2;
    __syncthreads();
    for (int off = 128; off; off >>= 1) {
        if (tid < off) { r0[tid] += r0[tid+off]; r1[tid] += r1[tid+off]; }
        __syncthreads();
    }
    float mu  = r0[0] * (1.0f/DIM);
    float var = r1[0] * (1.0f/DIM) - mu*mu;
    float rs  = rsqrtf(var + 1e-5f);
    __half* outp = g_hln + ((long)b*NTOK + m)*DIM;
    #pragma unroll
    for (int i = 0; i < 3; i++) {
        int c = tid + i*256;
        outp[c] = __float2half_rn((v[i] - mu) * rs * g[c] + be[c]);
    }
}

// ---------------- 2-stage masked mean pool + fused ECA ----------------
__global__ void k_pool1() {
    int b = blockIdx.z, part = blockIdx.y;
    int c = blockIdx.x * 256 + threadIdx.x;
    int cz = g_cntZ[b];
    int chunk = (cz + 15) / 16;
    int mlo = part * chunk, mhi = min(mlo + chunk, cz);
    float s = 0.0f;
    for (int m = mlo; m < mhi; m++) s += g_h2[((long)b*NTOK + m)*DIM + c];
    g_poolp[(b*16 + part)*DIM + c] = s;
}

__global__ void k_pool2(const float* __restrict__ w) {
    int b = blockIdx.x, c = threadIdx.x;
    __shared__ float pooled[DIM];
    float s = 0.0f;
    #pragma unroll
    for (int p = 0; p < 16; p++) s += g_poolp[(b*16 + p)*DIM + c];
    pooled[c] = s / fmaxf((float)g_cntZ[b], 1.0f);
    __syncthreads();
    float g = 0.0f;
    #pragma unroll
    for (int tt = 0; tt < 5; tt++) {
        int cc = c + tt - 2;
        if (cc >= 0 && cc < DIM) g += w[tt] * pooled[cc];
    }
    g_sig[b*DIM + c] = 1.0f / (1.0f + __expf(-g));
}

// ---------------- LTRM scatter ----------------
__global__ void k_ltrm(const float* __restrict__ x, float* __restrict__ out) {
    int b = blockIdx.y, m = blockIdx.x;
    if (m >= g_cntZ[b]) return;
    int tok = g_zidx[b*NTOK + m];
    long ro = ((long)b*NTOK + tok)*DIM;
    long ri = ((long)b*NTOK + m)*DIM;
    for (int c = threadIdx.x; c < DIM; c += 256)
        out[ro + c] = x[ro + c] + g_h2[ri + c] * g_sig[b*DIM + c];
}

// ---------------- launch: fork-join two streams inside capture ----------------
extern "C" void kernel_launch(void* const* d_in, const int* in_sizes, int n_in,
                              void* d_out, int out_size) {
    const float* x      = (const float*)d_in[0];
    const float* hint   = (const float*)d_in[1];
    const float* qkv_w  = (const float*)d_in[2];
    const float* qkv_b  = (const float*)d_in[3];
    const float* proj_w = (const float*)d_in[4];
    const float* proj_b = (const float*)d_in[5];
    const float* ln_g   = (const float*)d_in[6];
    const float* ln_b   = (const float*)d_in[7];
    const float* fc1_w  = (const float*)d_in[8];
    const float* fc1_b  = (const float*)d_in[9];
    const float* fc2_w  = (const float*)d_in[10];
    const float* fc2_b  = (const float*)d_in[11];
    const float* eca_w  = (const float*)d_in[12];
    float* out = (float*)d_out;

    __half *d_xh, *d_wqkv, *d_wproj, *d_wfc1, *d_wfc2, *d_oh, *d_hln, *d_h1;
    cudaGetSymbolAddress((void**)&d_xh,   g_xh);
    cudaGetSymbolAddress((void**)&d_wqkv, g_wqkv);
    cudaGetSymbolAddress((void**)&d_wproj,g_wproj);
    cudaGetSymbolAddress((void**)&d_wfc1, g_wfc1);
    cudaGetSymbolAddress((void**)&d_wfc2, g_wfc2);
    cudaGetSymbolAddress((void**)&d_oh,  g_oh);
    cudaGetSymbolAddress((void**)&d_hln, g_hln);
    cudaGetSymbolAddress((void**)&d_h1,  g_h1);

    cudaStream_t s2;
    cudaStreamCreateWithFlags(&s2, cudaStreamNonBlocking);
    cudaEvent_t e0, eCvt, eCompact, eEasy;
    cudaEventCreateWithFlags(&e0,       cudaEventDisableTiming);
    cudaEventCreateWithFlags(&eCvt,     cudaEventDisableTiming);
    cudaEventCreateWithFlags(&eCompact, cudaEventDisableTiming);
    cudaEventCreateWithFlags(&eEasy,    cudaEventDisableTiming);

    // fork: conversions on s2, edge-mask chain on stream0
    cudaEventRecord(e0, 0);
    cudaStreamWaitEvent(s2, e0, 0);
    k_cvtall<<<5376, 256, 0, s2>>>(x, qkv_w, proj_w, fc1_w, fc2_w);
    cudaEventRecord(eCvt, s2);

    k_edge   <<<BB*NTOK/8, 256>>>(hint);
    k_compact<<<BB, 1024>>>();
    cudaEventRecord(eCompact, 0);

    // edge path on stream0
    cudaStreamWaitEvent(0, eCvt, 0);
    k_gemm<0><<<dim3(3*DIM/128, NTOK/128, BB), 256>>>(x, d_xh, d_wqkv, qkv_b, out);
    k_attn   <<<dim3(NTOK/128, HEADS, BB), 256>>>();
    k_gemm<1><<<dim3(DIM/128, NTOK/128, BB), 256>>>(x, d_oh, d_wproj, proj_b, out);

    // easy path on s2
    cudaStreamWaitEvent(s2, eCompact, 0);
    k_ln     <<<dim3(NTOK, BB), 256, 0, s2>>>(x, ln_g, ln_b);
    k_gemm<2><<<dim3(HID/128, NTOK/128, BB), 256, 0, s2>>>(x, d_hln, d_wfc1, fc1_b, out);
    k_gemm<3><<<dim3(DIM/128, NTOK/128, BB), 256, 0, s2>>>(x, d_h1, d_wfc2, fc2_b, out);
    k_pool1  <<<dim3(DIM/256, 16, BB), 256, 0, s2>>>();
    k_pool2  <<<BB, DIM, 0, s2>>>(eca_w);
    k_ltrm   <<<dim3(NTOK, BB), 256, 0, s2>>>(x, out);
    cudaEventRecord(eEasy, s2);

    cudaStreamWaitEvent(0, eEasy, 0);

    cudaEventDestroy(e0);
    cudaEventDestroy(eCvt);
    cudaEventDestroy(eCompact);
    cudaEventDestroy(eEasy);
    cudaStreamDestroy(s2);
}

// round 10
// speedup vs baseline: 8.0022x; 1.0375x over previous
#include <cuda_runtime.h>
#include <cuda_fp16.h>
#include <math.h>
#include <cstdint>

#define BB     2
#define NTOK   4096
#define DIM    768
#define HEADS  12
#define HD     64
#define HID    1536
#define HINTR  1024

// ---------------- device scratch ----------------
__device__ int    g_edge[BB*NTOK];
__device__ int    g_cntE[BB];
__device__ int    g_cntZ[BB];
__device__ int    g_eidx[BB*NTOK];
__device__ int    g_zidx[BB*NTOK];
__device__ __half g_xh [(size_t)BB*NTOK*DIM];
__device__ __half g_wqkv[(size_t)DIM*3*DIM];
__device__ __half g_wproj[(size_t)DIM*DIM];
__device__ __half g_wfc1[(size_t)DIM*HID];
__device__ __half g_wfc2[(size_t)HID*DIM];
__device__ __half g_qh [(size_t)BB*HEADS*NTOK*HD];
__device__ __half g_kh [(size_t)BB*HEADS*NTOK*HD];
__device__ __half g_vh [(size_t)BB*HEADS*NTOK*HD];
__device__ __half g_oh [(size_t)BB*NTOK*DIM];
__device__ __half g_hln[(size_t)BB*NTOK*DIM];
__device__ __half g_h1 [(size_t)BB*NTOK*HID];
__device__ float  g_h2 [(size_t)BB*NTOK*DIM];
__device__ float  g_poolp[BB*16*DIM];
__device__ float  g_sig [BB*DIM];

// ---------------- asm helpers ----------------
__device__ __forceinline__ void mma16(float4& d, const unsigned* a, unsigned b0, unsigned b1) {
    asm volatile(
        "mma.sync.aligned.m16n8k16.row.col.f32.f16.f16.f32 "
        "{%0,%1,%2,%3}, {%4,%5,%6,%7}, {%8,%9}, {%0,%1,%2,%3};\n"
        : "+f"(d.x), "+f"(d.y), "+f"(d.z), "+f"(d.w)
        : "r"(a[0]), "r"(a[1]), "r"(a[2]), "r"(a[3]), "r"(b0), "r"(b1));
}
__device__ __forceinline__ void ldsm4(unsigned* r, const void* p) {
    unsigned a = (unsigned)__cvta_generic_to_shared(p);
    asm volatile("ldmatrix.sync.aligned.m8n8.x4.shared.b16 {%0,%1,%2,%3}, [%4];\n"
        : "=r"(r[0]), "=r"(r[1]), "=r"(r[2]), "=r"(r[3]) : "r"(a));
}
__device__ __forceinline__ void ldsm4t(unsigned* r, const void* p) {
    unsigned a = (unsigned)__cvta_generic_to_shared(p);
    asm volatile("ldmatrix.sync.aligned.m8n8.x4.trans.shared.b16 {%0,%1,%2,%3}, [%4];\n"
        : "=r"(r[0]), "=r"(r[1]), "=r"(r[2]), "=r"(r[3]) : "r"(a));
}
__device__ __forceinline__ void cpa16(void* smem, const void* gmem) {
    unsigned s = (unsigned)__cvta_generic_to_shared(smem);
    asm volatile("cp.async.cg.shared.global [%0], [%1], 16;\n" :: "r"(s), "l"(gmem));
}
__device__ __forceinline__ void cpa16z(void* smem, const void* gmem, bool pred) {
    unsigned s = (unsigned)__cvta_generic_to_shared(smem);
    int sz = pred ? 16 : 0;
    asm volatile("cp.async.cg.shared.global [%0], [%1], 16, %2;\n" :: "r"(s), "l"(gmem), "r"(sz));
}
__device__ __forceinline__ void cpa_commit() { asm volatile("cp.async.commit_group;\n"); }
__device__ __forceinline__ void cpa_wait1()  { asm volatile("cp.async.wait_group 1;\n"); }
__device__ __forceinline__ unsigned h2u(__half2 h) { return *(unsigned*)&h; }
__device__ __forceinline__ float ex2(float x) {
    float y; asm("ex2.approx.ftz.f32 %0, %1;" : "=f"(y) : "f"(x)); return y;
}

// ---------------- merged fp32 -> fp16 conversion ----------------
__global__ void k_cvtall(const float* __restrict__ x,  const float* __restrict__ w0,
                         const float* __restrict__ w1, const float* __restrict__ w2,
                         const float* __restrict__ w3) {
    int bx = blockIdx.x;
    const float* src; __half* dst; long base;
    if (bx < 3072)      { src = x;  dst = g_xh;    base = (long)bx * 2048; }
    else if (bx < 3936) { src = w0; dst = g_wqkv;  base = (long)(bx - 3072) * 2048; }
    else if (bx < 4224) { src = w1; dst = g_wproj; base = (long)(bx - 3936) * 2048; }
    else if (bx < 4800) { src = w2; dst = g_wfc1;  base = (long)(bx - 4224) * 2048; }
    else                { src = w3; dst = g_wfc2;  base = (long)(bx - 4800) * 2048; }
    long i = base + threadIdx.x * 8;
    float4 f0 = *(const float4*)(src + i);
    float4 f1 = *(const float4*)(src + i + 4);
    __half2 h[4] = { __floats2half2_rn(f0.x, f0.y), __floats2half2_rn(f0.z, f0.w),
                     __floats2half2_rn(f1.x, f1.y), __floats2half2_rn(f1.z, f1.w) };
    *(uint4*)(dst + i) = *(uint4*)h;
}

// ---------------- edge mask ----------------
__global__ void k_edge(const float* __restrict__ hint) {
    int warp = threadIdx.x >> 5, lane = threadIdx.x & 31;
    int token = blockIdx.x * 8 + warp;
    int b = token / NTOK, t = token % NTOK;
    int ty = t >> 6, tx = t & 63;
    const float* base = hint + (size_t)b*HINTR*HINTR + (size_t)(ty*16)*HINTR + tx*16;
    int r = lane >> 1, half = lane & 1;
    const float4* p = (const float4*)(base + (size_t)r*HINTR + half*8);
    float4 a = p[0], c = p[1];
    float s = a.x+a.y+a.z+a.w + c.x+c.y+c.z+c.w;
    #pragma unroll
    for (int off = 16; off; off >>= 1) s += __shfl_down_sync(0xffffffffu, s, off);
    if (lane == 0) {
        float mean = s * (1.0f/256.0f);
        g_edge[token] = (mean > 0.02f && mean < 0.98f) ? 1 : 0;
    }
}

// ---------------- compaction with folded fallback ----------------
__global__ void k_compact() {
    int b = blockIdx.x, tid = threadIdx.x;
    int t0 = tid * 4;
    int f[4]; int e = 0;
    #pragma unroll
    for (int i = 0; i < 4; i++) { f[i] = g_edge[b*NTOK + t0 + i]; e += f[i]; }
    int lane = tid & 31, wid = tid >> 5;
    int v = e;
    #pragma unroll
    for (int off = 1; off < 32; off <<= 1) {
        int n = __shfl_up_sync(0xffffffffu, v, off);
        if (lane >= off) v += n;
    }
    __shared__ int wsum[32];
    if (lane == 31) wsum[wid] = v;
    __syncthreads();
    if (wid == 0) {
        int wv = wsum[lane];
        #pragma unroll
        for (int off = 1; off < 32; off <<= 1) {
            int n = __shfl_up_sync(0xffffffffu, wv, off);
            if (lane >= off) wv += n;
        }
        wsum[lane] = wv;
    }
    __syncthreads();
    int tot = wsum[31];
    if (tot < 64) {
        #pragma unroll
        for (int i = 0; i < 4; i++) g_eidx[b*NTOK + t0 + i] = t0 + i;
        if (tid == 1023) { g_cntE[b] = NTOK; g_cntZ[b] = 0; }
        return;
    }
    int excl = v - e + (wid ? wsum[wid-1] : 0);
    int eoff = excl, zoff = t0 - excl;
    #pragma unroll
    for (int i = 0; i < 4; i++) {
        if (f[i]) g_eidx[b*NTOK + eoff++] = t0 + i;
        else      g_zidx[b*NTOK + zoff++] = t0 + i;
    }
    if (tid == 1023) { g_cntE[b] = tot; g_cntZ[b] = NTOK - tot; }
}

// ---------------- fp16 MMA GEMM: 3-stage ring, single barrier/iter ----------------
__device__ __forceinline__ float gelu_exact(float x) {
    return 0.5f * x * (1.0f + erff(x * 0.70710678118654752f));
}

#define GEMM_SMEM (3*(128*40 + 32*136)*2)   // 56832 B

template<int EPI>
__global__ void __launch_bounds__(256)
k_gemm(const float* __restrict__ xfull, const __half* __restrict__ A,
       const __half* __restrict__ W, const float* __restrict__ bias,
       float* __restrict__ dout)
{
    constexpr int K = (EPI == 3) ? HID : DIM;
    constexpr int N = (EPI == 0) ? 3*DIM : (EPI == 2 ? HID : DIM);
    constexpr int NT = K / 32;
    const int* cntp = (EPI >= 2) ? g_cntZ : g_cntE;

    int b = blockIdx.z;
    int M = cntp[b];
    int m0 = blockIdx.y * 128;
    if (m0 >= M) return;
    int n0 = blockIdx.x * 128;
    const __half* Ab = A + (long)b * NTOK * K;

    extern __shared__ __align__(16) __half smg[];
    __half* As_ = smg;                   // 3 bufs x 128 x 40
    __half* Bs_ = smg + 3*128*40;        // 3 bufs x 32 x 136
    #define AS(bf,m,k)  As_[(bf)*5120 + (m)*40 + (k)]
    #define BS(bf,kr,n) Bs_[(bf)*4352 + (kr)*136 + (n)]

    int tid = threadIdx.x;
    int w = tid >> 5, lane = tid & 31;
    int wm = (w >> 2) * 64, wn = (w & 3) * 32;
    int qr = lane >> 2, qc = lane & 3;

    int  mA[2], cA[2], krB[2], cB[2];
    long arow[2];
    #pragma unroll
    for (int t = 0; t < 2; t++) {
        int task = tid + 256*t;
        mA[t] = task >> 2; cA[t] = (task & 3) * 8;
        int gm = m0 + mA[t];
        arow[t] = (gm < M) ? (long)((EPI == 0) ? g_eidx[b*NTOK + gm] : gm) * K : -1;
        krB[t] = task >> 4; cB[t] = (task & 15) * 8;
    }

    auto issue = [&](int k0, int bf) {
        #pragma unroll
        for (int t = 0; t < 2; t++) {
            const __half* asrc = (arow[t] >= 0) ? (Ab + arow[t] + k0 + cA[t]) : Ab;
            cpa16z(&AS(bf, mA[t], cA[t]), asrc, arow[t] >= 0);
            cpa16(&BS(bf, krB[t], cB[t]), W + (long)(k0 + krB[t])*N + n0 + cB[t]);
        }
    };

    float4 acc[4][4];
    #pragma unroll
    for (int i = 0; i < 4; i++)
        #pragma unroll
        for (int j = 0; j < 4; j++) acc[i][j] = make_float4(0,0,0,0);

    issue(0, 0); cpa_commit();
    issue(32, 1); cpa_commit();

    int bf = 0;
    #pragma unroll 1
    for (int it = 0; it < NT; it++) {
        cpa_wait1();
        __syncthreads();
        unsigned bfr[4][4];
        #pragma unroll
        for (int ni = 0; ni < 4; ni++)
            ldsm4t(bfr[ni], &BS(bf, lane, wn + ni*8));
        #pragma unroll
        for (int ks = 0; ks < 2; ks++) {
            unsigned afr[4][4];
            #pragma unroll
            for (int mi = 0; mi < 4; mi++)
                ldsm4(afr[mi], &AS(bf, wm + mi*16 + (lane & 15), ks*16 + (lane >> 4)*8));
            #pragma unroll
            for (int ni = 0; ni < 4; ni++)
                #pragma unroll
                for (int mi = 0; mi < 4; mi++)
                    mma16(acc[mi][ni], afr[mi], bfr[ni][ks*2], bfr[ni][ks*2+1]);
        }
        if (it + 2 < NT) {
            int nb = bf + 2; if (nb >= 3) nb -= 3;
            issue((it + 2) * 32, nb);
        }
        cpa_commit();
        if (++bf == 3) bf = 0;
    }

    #pragma unroll
    for (int mi = 0; mi < 4; mi++) {
        int rowA = m0 + wm + mi*16 + qr;
        int rowB = rowA + 8;
        #pragma unroll
        for (int ni = 0; ni < 4; ni++) {
            int col = n0 + wn + ni*8 + qc*2;
            float b0v = bias[col], b1v = bias[col+1];
            float vx = acc[mi][ni].x + b0v, vy = acc[mi][ni].y + b1v;
            float vz = acc[mi][ni].z + b0v, vw = acc[mi][ni].w + b1v;
            if (EPI == 0) {
                int part = col / DIM, cc = col - part*DIM;
                __half* dst = (part == 0) ? g_qh : (part == 1) ? g_kh : g_vh;
                int h = cc >> 6, d = cc & 63;
                long hb = ((long)b*HEADS + h)*NTOK;
                if (rowA < M) *(__half2*)&dst[(hb + rowA)*HD + d] = __floats2half2_rn(vx, vy);
                if (rowB < M) *(__half2*)&dst[(hb + rowB)*HD + d] = __floats2half2_rn(vz, vw);
            } else if (EPI == 1) {
                if (rowA < M) {
                    long o = ((long)b*NTOK + g_eidx[b*NTOK + rowA])*DIM + col;
                    *(float2*)&dout[o] = make_float2(vx + xfull[o], vy + xfull[o+1]);
                }
                if (rowB < M) {
                    long o = ((long)b*NTOK + g_eidx[b*NTOK + rowB])*DIM + col;
                    *(float2*)&dout[o] = make_float2(vz + xfull[o], vw + xfull[o+1]);
                }
            } else if (EPI == 2) {
                if (rowA < M) *(__half2*)&g_h1[((long)b*NTOK + rowA)*HID + col] =
                    __floats2half2_rn(gelu_exact(gelu_exact(vx)), gelu_exact(gelu_exact(vy)));
                if (rowB < M) *(__half2*)&g_h1[((long)b*NTOK + rowB)*HID + col] =
                    __floats2half2_rn(gelu_exact(gelu_exact(vz)), gelu_exact(gelu_exact(vw)));
            } else {
                if (rowA < M) *(float2*)&g_h2[((long)b*NTOK + rowA)*DIM + col] = make_float2(vx, vy);
                if (rowB < M) *(float2*)&g_h2[((long)b*NTOK + rowB)*DIM + col] = make_float2(vz, vw);
            }
        }
    }
    #undef AS
    #undef BS
}

// ---------------- fp16 flash attention: 8 warps, 128 q/block, KT=64, 3-stage ring ----------------
#define KT 64
#define ATTN_SMEM (3*KT*72*2*2)   // 55296 B

__global__ void __launch_bounds__(256) k_attn() {
    int b = blockIdx.z, h = blockIdx.y;
    int M = g_cntE[b];
    int m0 = blockIdx.x * 128;
    if (m0 >= M) return;
    int tid = threadIdx.x, w = tid >> 5, lane = tid & 31;
    int qr = lane >> 2, qc = lane & 3;
    long base = ((long)b*HEADS + h)*NTOK*HD;

    extern __shared__ __align__(16) __half sma[];
    __half* Ks_ = sma;              // 3 x 64 x 72
    __half* Vs_ = sma + 3*KT*72;
    #define KS(bf,r,c) Ks_[(bf)*(KT*72) + (r)*72 + (c)]
    #define VS(bf,r,c) Vs_[(bf)*(KT*72) + (r)*72 + (c)]

    int r0 = m0 + w*16 + qr, r1 = r0 + 8;
    bool v0 = r0 < M, v1 = r1 < M;
    const __half* q0p = g_qh + base + (long)r0*HD;
    const __half* q1p = g_qh + base + (long)r1*HD;
    unsigned qf[4][4];
    #pragma unroll
    for (int ks = 0; ks < 4; ks++) {
        int c = ks*16 + qc*2;
        qf[ks][0] = v0 ? *(const unsigned*)&q0p[c]   : 0u;
        qf[ks][1] = v1 ? *(const unsigned*)&q1p[c]   : 0u;
        qf[ks][2] = v0 ? *(const unsigned*)&q0p[c+8] : 0u;
        qf[ks][3] = v1 ? *(const unsigned*)&q1p[c+8] : 0u;
    }

    // loader: K 512 chunks + V 512 chunks (16B each); 4 tasks/thread
    auto issue = [&](int kb, int bf) {
        #pragma unroll
        for (int t = 0; t < 4; t++) {
            int task = tid + 256*t;            // 0..1023
            int mat  = task >> 9;              // 0 = K, 1 = V
            int t2   = task & 511;
            int row  = t2 >> 3;                // 0..63
            int c8   = (t2 & 7) * 8;
            bool ok = (kb + row) < M;
            const __half* src = (mat ? g_vh : g_kh) + base + (long)(kb + (ok ? row : 0))*HD + c8;
            if (mat) cpa16z(&VS(bf, row, c8), src, ok);
            else     cpa16z(&KS(bf, row, c8), src, ok);
        }
    };

    float4 oacc[8];
    #pragma unroll
    for (int i = 0; i < 8; i++) oacc[i] = make_float4(0,0,0,0);
    float mx0 = -1e30f, mx1 = -1e30f, l0 = 0.0f, l1 = 0.0f;
    const float SC = 0.125f * 1.44269504088896340736f;

    int ntiles = (M + KT - 1) / KT;
    issue(0, 0); cpa_commit();
    if (ntiles > 1) issue(KT, 1);
    cpa_commit();

    int bf = 0;
    #pragma unroll 1
    for (int kt = 0; kt < ntiles; kt++) {
        int kb = kt * KT;
        cpa_wait1();
        __syncthreads();

        // S = Q K^T : 8 n-tiles of 8 keys
        float4 s[8];
        #pragma unroll
        for (int nt = 0; nt < 8; nt++) s[nt] = make_float4(0,0,0,0);
        #pragma unroll
        for (int dh = 0; dh < 2; dh++) {
            #pragma unroll
            for (int nt = 0; nt < 8; nt++) {
                unsigned kf[4];
                ldsm4(kf, &KS(bf, nt*8 + (lane & 7), (lane >> 3)*8 + dh*32));
                mma16(s[nt], qf[dh*2],     kf[0], kf[1]);
                mma16(s[nt], qf[dh*2 + 1], kf[2], kf[3]);
            }
        }
        // scale, mask, row max
        float t0 = -1e30f, t1 = -1e30f;
        #pragma unroll
        for (int nt = 0; nt < 8; nt++) {
            s[nt].x *= SC; s[nt].y *= SC; s[nt].z *= SC; s[nt].w *= SC;
            int c0 = kb + nt*8 + qc*2;
            if (c0     >= M) { s[nt].x = -1e30f; s[nt].z = -1e30f; }
            if (c0 + 1 >= M) { s[nt].y = -1e30f; s[nt].w = -1e30f; }
            t0 = fmaxf(t0, fmaxf(s[nt].x, s[nt].y));
            t1 = fmaxf(t1, fmaxf(s[nt].z, s[nt].w));
        }
        t0 = fmaxf(t0, __shfl_xor_sync(0xffffffffu, t0, 1));
        t0 = fmaxf(t0, __shfl_xor_sync(0xffffffffu, t0, 2));
        t1 = fmaxf(t1, __shfl_xor_sync(0xffffffffu, t1, 1));
        t1 = fmaxf(t1, __shfl_xor_sync(0xffffffffu, t1, 2));
        float nm0 = fmaxf(mx0, t0), nm1 = fmaxf(mx1, t1);
        bool nochg = (nm0 == mx0) && (nm1 == mx1);
        if (!__all_sync(0xffffffffu, nochg)) {
            float cr0 = ex2(mx0 - nm0), cr1 = ex2(mx1 - nm1);
            l0 *= cr0; l1 *= cr1;
            #pragma unroll
            for (int i = 0; i < 8; i++) {
                oacc[i].x *= cr0; oacc[i].y *= cr0;
                oacc[i].z *= cr1; oacc[i].w *= cr1;
            }
        }
        mx0 = nm0; mx1 = nm1;

        // exp2 -> fp16 A-frags (64 keys = 4 ks-steps of 16)
        float ps0 = 0.0f, ps1 = 0.0f;
        unsigned pa[4][4];
        #pragma unroll
        for (int nt = 0; nt < 8; nt++) {
            float px = ex2(s[nt].x - mx0), py = ex2(s[nt].y - mx0);
            float pz = ex2(s[nt].z - mx1), pw = ex2(s[nt].w - mx1);
            ps0 += px + py; ps1 += pz + pw;
            int ks = nt >> 1, hi = (nt & 1) * 2;
            pa[ks][hi]     = h2u(__floats2half2_rn(px, py));
            pa[ks][hi + 1] = h2u(__floats2half2_rn(pz, pw));
        }
        ps0 += __shfl_xor_sync(0xffffffffu, ps0, 1);
        ps0 += __shfl_xor_sync(0xffffffffu, ps0, 2);
        ps1 += __shfl_xor_sync(0xffffffffu, ps1, 1);
        ps1 += __shfl_xor_sync(0xffffffffu, ps1, 2);
        l0 += ps0; l1 += ps1;

        // O += P V : 4 ks-steps of 16 keys, 8 n-tiles over HD
        #pragma unroll
        for (int ks = 0; ks < 4; ks++) {
            unsigned vf[4][4];
            #pragma unroll
            for (int dp = 0; dp < 4; dp++)
                ldsm4t(vf[dp], &VS(bf, 16*ks + ((lane >> 3) & 1)*8 + (lane & 7),
                                   dp*16 + (lane >> 4)*8));
            #pragma unroll
            for (int nt = 0; nt < 8; nt++)
                mma16(oacc[nt], pa[ks], vf[nt >> 1][(nt & 1)*2], vf[nt >> 1][(nt & 1)*2 + 1]);
        }

        if (kt + 2 < ntiles) {
            int nb = bf + 2; if (nb >= 3) nb -= 3;
            issue(kb + 2*KT, nb);
        }
        cpa_commit();
        if (++bf == 3) bf = 0;
    }

    float inv0 = 1.0f / l0, inv1 = 1.0f / l1;
    #pragma unroll
    for (int nt = 0; nt < 8; nt++) {
        int col = h*64 + nt*8 + qc*2;
        if (v0) *(__half2*)&g_oh[((long)b*NTOK + r0)*DIM + col] =
            __floats2half2_rn(oacc[nt].x * inv0, oacc[nt].y * inv0);
        if (v1) *(__half2*)&g_oh[((long)b*NTOK + r1)*DIM + col] =
            __floats2half2_rn(oacc[nt].z * inv1, oacc[nt].w * inv1);
    }
    #undef KS
    #undef VS
}

// ---------------- LayerNorm on easy rows (fp16 out) ----------------
__global__ void k_ln(const float* __restrict__ x, const float* __restrict__ g,
                     const float* __restrict__ be) {
    int b = blockIdx.y, m = blockIdx.x;
    if (m >= g_cntZ[b]) return;
    int tok = g_zidx[b*NTOK + m];
    const float* row = x + ((long)b*NTOK + tok)*DIM;
    int tid = threadIdx.x;
    float v[3];
    float s = 0.0f, s2 = 0.0f;
    #pragma unroll
    for (int i = 0; i < 3; i++) {
        v[i] = row[tid + i*256];
        s += v[i]; s2 += v[i]*v[i];
    }
    __shared__ float r0[256], r1[256];
    r0[tid] = s; r1[tid] = s2;
    __syncthreads();
    for (int off = 128; off; off >>= 1) {
        if (tid < off) { r0[tid] += r0[tid+off]; r1[tid] += r1[tid+off]; }
        __syncthreads();
    }
    float mu  = r0[0] * (1.0f/DIM);
    float var = r1[0] * (1.0f/DIM) - mu*mu;
    float rs  = rsqrtf(var + 1e-5f);
    __half* outp = g_hln + ((long)b*NTOK + m)*DIM;
    #pragma unroll
    for (int i = 0; i < 3; i++) {
        int c = tid + i*256;
        outp[c] = __float2half_rn((v[i] - mu) * rs * g[c] + be[c]);
    }
}

// ---------------- 2-stage masked mean pool + fused ECA ----------------
__global__ void k_pool1() {
    int b = blockIdx.z, part = blockIdx.y;
    int c = blockIdx.x * 256 + threadIdx.x;
    int cz = g_cntZ[b];
    int chunk = (cz + 15) / 16;
    int mlo = part * chunk, mhi = min(mlo + chunk, cz);
    float s = 0.0f;
    for (int m = mlo; m < mhi; m++) s += g_h2[((long)b*NTOK + m)*DIM + c];
    g_poolp[(b*16 + part)*DIM + c] = s;
}

__global__ void k_pool2(const float* __restrict__ w) {
    int b = blockIdx.x, c = threadIdx.x;
    __shared__ float pooled[DIM];
    float s = 0.0f;
    #pragma unroll
    for (int p = 0; p < 16; p++) s += g_poolp[(b*16 + p)*DIM + c];
    pooled[c] = s / fmaxf((float)g_cntZ[b], 1.0f);
    __syncthreads();
    float g = 0.0f;
    #pragma unroll
    for (int tt = 0; tt < 5; tt++) {
        int cc = c + tt - 2;
        if (cc >= 0 && cc < DIM) g += w[tt] * pooled[cc];
    }
    g_sig[b*DIM + c] = 1.0f / (1.0f + __expf(-g));
}

// ---------------- LTRM scatter ----------------
__global__ void k_ltrm(const float* __restrict__ x, float* __restrict__ out) {
    int b = blockIdx.y, m = blockIdx.x;
    if (m >= g_cntZ[b]) return;
    int tok = g_zidx[b*NTOK + m];
    long ro = ((long)b*NTOK + tok)*DIM;
    long ri = ((long)b*NTOK + m)*DIM;
    for (int c = threadIdx.x; c < DIM; c += 256)
        out[ro + c] = x[ro + c] + g_h2[ri + c] * g_sig[b*DIM + c];
}

// ---------------- launch ----------------
extern "C" void kernel_launch(void* const* d_in, const int* in_sizes, int n_in,
                              void* d_out, int out_size) {
    const float* x      = (const float*)d_in[0];
    const float* hint   = (const float*)d_in[1];
    const float* qkv_w  = (const float*)d_in[2];
    const float* qkv_b  = (const float*)d_in[3];
    const float* proj_w = (const float*)d_in[4];
    const float* proj_b = (const float*)d_in[5];
    const float* ln_g   = (const float*)d_in[6];
    const float* ln_b   = (const float*)d_in[7];
    const float* fc1_w  = (const float*)d_in[8];
    const float* fc1_b  = (const float*)d_in[9];
    const float* fc2_w  = (const float*)d_in[10];
    const float* fc2_b  = (const float*)d_in[11];
    const float* eca_w  = (const float*)d_in[12];
    float* out = (float*)d_out;

    __half *d_xh, *d_wqkv, *d_wproj, *d_wfc1, *d_wfc2, *d_oh, *d_hln, *d_h1;
    cudaGetSymbolAddress((void**)&d_xh,   g_xh);
    cudaGetSymbolAddress((void**)&d_wqkv, g_wqkv);
    cudaGetSymbolAddress((void**)&d_wproj,g_wproj);
    cudaGetSymbolAddress((void**)&d_wfc1, g_wfc1);
    cudaGetSymbolAddress((void**)&d_wfc2, g_wfc2);
    cudaGetSymbolAddress((void**)&d_oh,  g_oh);
    cudaGetSymbolAddress((void**)&d_hln, g_hln);
    cudaGetSymbolAddress((void**)&d_h1,  g_h1);

    static bool attr_done = false;
    if (!attr_done) {
        cudaFuncSetAttribute(k_gemm<0>, cudaFuncAttributeMaxDynamicSharedMemorySize, GEMM_SMEM);
        cudaFuncSetAttribute(k_gemm<1>, cudaFuncAttributeMaxDynamicSharedMemorySize, GEMM_SMEM);
        cudaFuncSetAttribute(k_gemm<2>, cudaFuncAttributeMaxDynamicSharedMemorySize, GEMM_SMEM);
        cudaFuncSetAttribute(k_gemm<3>, cudaFuncAttributeMaxDynamicSharedMemorySize, GEMM_SMEM);
        cudaFuncSetAttribute(k_attn,    cudaFuncAttributeMaxDynamicSharedMemorySize, ATTN_SMEM);
        attr_done = true;
    }

    cudaStream_t s2;
    cudaStreamCreateWithFlags(&s2, cudaStreamNonBlocking);
    cudaEvent_t e0, eCvt, eCompact, eEasy;
    cudaEventCreateWithFlags(&e0,       cudaEventDisableTiming);
    cudaEventCreateWithFlags(&eCvt,     cudaEventDisableTiming);
    cudaEventCreateWithFlags(&eCompact, cudaEventDisableTiming);
    cudaEventCreateWithFlags(&eEasy,    cudaEventDisableTiming);

    cudaEventRecord(e0, 0);
    cudaStreamWaitEvent(s2, e0, 0);
    k_cvtall<<<5376, 256, 0, s2>>>(x, qkv_w, proj_w, fc1_w, fc2_w);
    cudaEventRecord(eCvt, s2);

    k_edge   <<<BB*NTOK/8, 256>>>(hint);
    k_compact<<<BB, 1024>>>();
    cudaEventRecord(eCompact, 0);

    // edge path on stream0
    cudaStreamWaitEvent(0, eCvt, 0);
    k_gemm<0><<<dim3(3*DIM/128, NTOK/128, BB), 256, GEMM_SMEM>>>(x, d_xh, d_wqkv, qkv_b, out);
    k_attn   <<<dim3(NTOK/128, HEADS, BB), 256, ATTN_SMEM>>>();
    k_gemm<1><<<dim3(DIM/128, NTOK/128, BB), 256, GEMM_SMEM>>>(x, d_oh, d_wproj, proj_b, out);

    // easy path on s2
    cudaStreamWaitEvent(s2, eCompact, 0);
    k_ln     <<<dim3(NTOK, BB), 256, 0, s2>>>(x, ln_g, ln_b);
    k_gemm<2><<<dim3(HID/128, NTOK/128, BB), 256, GEMM_SMEM, s2>>>(x, d_hln, d_wfc1, fc1_b, out);
    k_gemm<3><<<dim3(DIM/128, NTOK/128, BB), 256, GEMM_SMEM, s2>>>(x, d_h1, d_wfc2, fc2_b, out);
    k_pool1  <<<dim3(DIM/256, 16, BB), 256, 0, s2>>>();
    k_pool2  <<<BB, DIM, 0, s2>>>(eca_w);
    k_ltrm   <<<dim3(NTOK, BB), 256, 0, s2>>>(x, out);
    cudaEventRecord(eEasy, s2);

    cudaStreamWaitEvent(0, eEasy, 0);

    cudaEventDestroy(e0);
    cudaEventDestroy(eCvt);
    cudaEventDestroy(eCompact);
    cudaEventDestroy(eEasy);
    cudaStreamDestroy(s2);
}